// round 14
// baseline (speedup 1.0000x reference)
#include <cuda_runtime.h>
#include <cuda_bf16.h>
#include <math.h>
#include <stdint.h>

#define BATCH 4
#define SEQ   2048
#define DM    1024
#define NH    16
#define HD    64
#define MTOT  (BATCH*SEQ)   // 8192

// ---------------- scratch (__device__ statics; allocation-guard safe) -------
__device__ float g_v[(size_t)BATCH*NH*SEQ*HD];

__device__ __nv_bfloat16 s_xhi[(size_t)MTOT*DM];
__device__ __nv_bfloat16 s_xlo[(size_t)MTOT*DM];
__device__ __nv_bfloat16 s_whi[(size_t)3*DM*DM];
__device__ __nv_bfloat16 s_wlo[(size_t)3*DM*DM];
__device__ __nv_bfloat16 s_ohi[(size_t)DM*DM];
__device__ __nv_bfloat16 s_olo[(size_t)DM*DM];
__device__ __nv_bfloat16 s_ahi[(size_t)MTOT*DM];
__device__ __nv_bfloat16 s_alo[(size_t)MTOT*DM];

__device__ __nv_bfloat16 s_qhi[(size_t)BATCH*NH*SEQ*HD];
__device__ __nv_bfloat16 s_qlo[(size_t)BATCH*NH*SEQ*HD];
__device__ __nv_bfloat16 s_khi[(size_t)BATCH*NH*SEQ*HD];
__device__ __nv_bfloat16 s_klo[(size_t)BATCH*NH*SEQ*HD];
__device__ __nv_bfloat16 s_vthi[(size_t)BATCH*NH*HD*SEQ];  // [bh][d][s]
__device__ __nv_bfloat16 s_vtlo[(size_t)BATCH*NH*HD*SEQ];

// ---------------- helpers ----------------------------------------------------
__device__ __forceinline__ uint32_t smem_u32(const void* p) {
    uint32_t a;
    asm("{ .reg .u64 t; cvta.to.shared.u64 t, %1; cvt.u32.u64 %0, t; }"
        : "=r"(a) : "l"(p));
    return a;
}
#define LDMX4(d, a) \
    asm volatile("ldmatrix.sync.aligned.m8n8.x4.shared.b16 {%0,%1,%2,%3}, [%4];" \
                 : "=r"((d)[0]), "=r"((d)[1]), "=r"((d)[2]), "=r"((d)[3]) : "r"(a))
#define MMA16816(c, a, b0, b1) \
    asm volatile("mma.sync.aligned.m16n8k16.row.col.f32.bf16.bf16.f32 " \
                 "{%0,%1,%2,%3}, {%4,%5,%6,%7}, {%8,%9}, {%0,%1,%2,%3};" \
                 : "+f"((c)[0]), "+f"((c)[1]), "+f"((c)[2]), "+f"((c)[3]) \
                 : "r"((a)[0]), "r"((a)[1]), "r"((a)[2]), "r"((a)[3]), \
                   "r"(b0), "r"(b1))
#define CPASYNC16(sa, gp) \
    asm volatile("cp.async.cg.shared.global [%0], [%1], 16;" :: "r"(sa), "l"(gp))

__device__ __forceinline__ uint32_t pack_bf2(float a, float b) {
    __nv_bfloat162 t;
    t.x = __float2bfloat16(a);
    t.y = __float2bfloat16(b);
    return *reinterpret_cast<uint32_t*>(&t);
}
__device__ __forceinline__ void split2(float a, float b, uint32_t& hi, uint32_t& lo) {
    __nv_bfloat16 ah = __float2bfloat16(a), bh = __float2bfloat16(b);
    __nv_bfloat162 h; h.x = ah; h.y = bh;
    hi = *reinterpret_cast<uint32_t*>(&h);
    lo = pack_bf2(a - __bfloat162float(ah), b - __bfloat162float(bh));
}

// ---------------------------------------------------------------------------
// fp32 -> bf16 hi/lo split of all three inputs, ONE launch, float4 vectorized
// ---------------------------------------------------------------------------
#define N_X (MTOT*DM)        // 8388608
#define N_W (3*DM*DM)        // 3145728
#define N_O (DM*DM)          // 1048576

__global__ __launch_bounds__(256) void cvt_split3(
    const float* __restrict__ x, const float* __restrict__ wq,
    const float* __restrict__ wo)
{
    int i4 = blockIdx.x * 256 + threadIdx.x;   // float4 index
    int i = i4 * 4;
    const float* src;
    __nv_bfloat16 *hi, *lo;
    int j;
    if (i < N_X)              { src = x;  hi = s_xhi; lo = s_xlo; j = i; }
    else if (i < N_X + N_W)   { src = wq; hi = s_whi; lo = s_wlo; j = i - N_X; }
    else                      { src = wo; hi = s_ohi; lo = s_olo; j = i - N_X - N_W; }
    float4 v = *(const float4*)(src + j);
    uint32_t h0, l0, h1, l1;
    split2(v.x, v.y, h0, l0);
    split2(v.z, v.w, h1, l1);
    *(uint2*)(hi + j) = make_uint2(h0, h1);
    *(uint2*)(lo + j) = make_uint2(l0, l1);
}

// ---------------------------------------------------------------------------
// Split-bf16 tensor-core GEMM (frozen r13). 2-stage, one barrier per chunk.
// mode 0: OUT store. mode 1: q/k -> RoPE+split; v -> g_v fp32.
// ---------------------------------------------------------------------------
#define GEMM_SMEM 65536

__device__ __forceinline__ void stage_chunk(
    uint32_t smbase, int p, int c,
    const __nv_bfloat16* s0, const __nv_bfloat16* s1,
    const __nv_bfloat16* s2, const __nv_bfloat16* s3, int tid)
{
    const __nv_bfloat16* srcs[4] = {s0, s1, s2, s3};
    const uint32_t bufb = smbase + (uint32_t)p * 32768u;
#pragma unroll
    for (int comp = 0; comp < 4; comp++) {
        const __nv_bfloat16* s = srcs[comp] + c * 32;
        const uint32_t db = bufb + (uint32_t)comp * 8192u;
#pragma unroll
        for (int t = 0; t < 2; t++) {
            int idx = tid + t * 256;
            int row = idx >> 2, c16 = idx & 3;
            const void* gp = s + (size_t)row * DM + c16 * 8;
            uint32_t sw = db + (uint32_t)(row * 64)
                        + ((uint32_t)(c16 ^ ((row >> 1) & 3)) << 4);
            CPASYNC16(sw, gp);
        }
    }
    asm volatile("cp.async.commit_group;" ::: "memory");
}

__global__ __launch_bounds__(256, 2) void gemm_mma(
    const __nv_bfloat16* __restrict__ Ahi, const __nv_bfloat16* __restrict__ Alo,
    const __nv_bfloat16* __restrict__ Bhi, const __nv_bfloat16* __restrict__ Blo,
    float* __restrict__ OUT, int mode)
{
    extern __shared__ __align__(128) char smraw[];
    const uint32_t smbase = smem_u32(smraw);
    const int tid  = threadIdx.x;
    const int wid  = tid >> 5;
    const int lane = tid & 31;
    const int wm   = wid >> 2;
    const int wn   = wid & 3;
    const int n0   = blockIdx.x * 128;
    const int m0   = blockIdx.y * 128;

    const __nv_bfloat16* gAhi = Ahi + (size_t)m0 * DM;
    const __nv_bfloat16* gAlo = Alo + (size_t)m0 * DM;
    const __nv_bfloat16* gBhi = Bhi + (size_t)n0 * DM;
    const __nv_bfloat16* gBlo = Blo + (size_t)n0 * DM;

    float C[4][4][4];
#pragma unroll
    for (int i = 0; i < 4; i++)
#pragma unroll
        for (int j = 0; j < 4; j++)
#pragma unroll
            for (int k = 0; k < 4; k++) C[i][j][k] = 0.f;

    const int g = lane >> 3, r = lane & 7;

    stage_chunk(smbase, 0, 0, gAhi, gAlo, gBhi, gBlo, tid);

    for (int c = 0; c < 32; c++) {
        const int p = c & 1;
        asm volatile("cp.async.wait_group 0;" ::: "memory");
        __syncthreads();
        if (c + 1 < 32)
            stage_chunk(smbase, p ^ 1, c + 1, gAhi, gAlo, gBhi, gBlo, tid);

        const uint32_t ab = smbase + (uint32_t)p * 32768u;
#pragma unroll
        for (int kh = 0; kh < 2; kh++) {
            const int kkc = kh * 2;
            uint32_t bhi[4][2], blo[4][2];
#pragma unroll
            for (int bp = 0; bp < 2; bp++) {
                int row = wn * 32 + bp * 16 + (g >> 1) * 8 + r;
                int c16 = kkc + (g & 1);
                uint32_t sw = (uint32_t)(row * 64)
                            + ((uint32_t)(c16 ^ ((row >> 1) & 3)) << 4);
                uint32_t t[4];
                LDMX4(t, ab + 16384u + sw);
                bhi[bp*2][0] = t[0]; bhi[bp*2][1] = t[1];
                bhi[bp*2+1][0] = t[2]; bhi[bp*2+1][1] = t[3];
                LDMX4(t, ab + 24576u + sw);
                blo[bp*2][0] = t[0]; blo[bp*2][1] = t[1];
                blo[bp*2+1][0] = t[2]; blo[bp*2+1][1] = t[3];
            }
#pragma unroll
            for (int mf = 0; mf < 4; mf++) {
                int row = wm * 64 + mf * 16 + (g & 1) * 8 + r;
                int c16 = kkc + (g >> 1);
                uint32_t sw = (uint32_t)(row * 64)
                            + ((uint32_t)(c16 ^ ((row >> 1) & 3)) << 4);
                uint32_t ah[4], al[4];
                LDMX4(ah, ab + sw);
                LDMX4(al, ab + 8192u + sw);
#pragma unroll
                for (int nf = 0; nf < 4; nf++) {
                    MMA16816(C[mf][nf], ah, bhi[nf][0], bhi[nf][1]);
                    MMA16816(C[mf][nf], ah, blo[nf][0], blo[nf][1]);
                    MMA16816(C[mf][nf], al, bhi[nf][0], bhi[nf][1]);
                }
            }
        }
    }

    // ---------------- epilogue ----------------
#pragma unroll
    for (int mf = 0; mf < 4; mf++) {
#pragma unroll
        for (int nf = 0; nf < 4; nf++) {
            int row0 = m0 + wm * 64 + mf * 16 + (lane >> 2);
            int col  = n0 + wn * 32 + nf * 8 + (lane & 3) * 2;   // even
            if (mode == 0) {
                *(float2*)(OUT + (size_t)row0 * DM + col) =
                    make_float2(C[mf][nf][0], C[mf][nf][1]);
                *(float2*)(OUT + (size_t)(row0 + 8) * DM + col) =
                    make_float2(C[mf][nf][2], C[mf][nf][3]);
            } else {
                const int which = col >> 10;
                const int h  = (col & 1023) >> 6;
                const int dd = col & 63;
                if (which == 2) {
#pragma unroll
                    for (int rr = 0; rr < 2; rr++) {
                        int row = row0 + rr * 8;
                        int b = row >> 11, s = row & 2047;
                        float* vp = g_v + (((size_t)(b * NH + h) * SEQ + s) * HD) + dd;
                        *(float2*)vp = make_float2(C[mf][nf][2*rr], C[mf][nf][2*rr+1]);
                    }
                } else {
                    // Q/K: RoPE (neg-sin interleaved, validated r6) + split
                    __nv_bfloat16* dhi = (which == 0) ? s_qhi : s_khi;
                    __nv_bfloat16* dlo = (which == 0) ? s_qlo : s_klo;
                    const float inv_f = expf((float)dd * -0.14391156831212787f);
#pragma unroll
                    for (int rr = 0; rr < 2; rr++) {
                        int row = row0 + rr * 8;
                        int b = row >> 11, s = row & 2047;
                        float cs, sn;
                        sincosf((float)s * inv_f, &cs, &sn);
                        float x0 = C[mf][nf][2*rr], x1 = C[mf][nf][2*rr+1];
                        float y0 = x0 * cs + x1 * sn;
                        float y1 = x1 * cs - x0 * sn;
                        uint32_t hi, lo;
                        split2(y0, y1, hi, lo);
                        size_t off = (((size_t)(b * NH + h) * SEQ + s) * HD) + dd;
                        *(uint32_t*)(dhi + off) = hi;
                        *(uint32_t*)(dlo + off) = lo;
                    }
                }
            }
        }
    }
}

// ---------------------------------------------------------------------------
// V transpose + split: g_v fp32 [bh][s][d] -> s_vthi/s_vtlo [bh][d][s]
// ---------------------------------------------------------------------------
__global__ __launch_bounds__(256) void transpose_v() {
    __shared__ float t[64][65];
    const int bh = blockIdx.x, s0 = blockIdx.y * 64;
    const int tid = threadIdx.x;
    const float* src = g_v + (size_t)bh * SEQ * HD + (size_t)s0 * HD;
#pragma unroll
    for (int i = 0; i < 4; i++) {
        int idx = tid + i * 256;
        int rr = idx >> 4, cc = (idx & 15) << 2;
        float4 v = *(const float4*)(src + rr * HD + cc);
        t[rr][cc] = v.x; t[rr][cc+1] = v.y; t[rr][cc+2] = v.z; t[rr][cc+3] = v.w;
    }
    __syncthreads();
    __nv_bfloat16* dhi = s_vthi + (size_t)bh * HD * SEQ + s0;
    __nv_bfloat16* dlo = s_vtlo + (size_t)bh * HD * SEQ + s0;
#pragma unroll
    for (int i = 0; i < 8; i++) {
        int idx = tid + i * 256;
        int d = idx >> 5, sp = (idx & 31) << 1;
        uint32_t hi, lo;
        split2(t[sp][d], t[sp+1][d], hi, lo);
        *(uint32_t*)(dhi + (size_t)d * SEQ + sp) = hi;
        *(uint32_t*)(dlo + (size_t)d * SEQ + sp) = lo;
    }
}

// ---------------------------------------------------------------------------
// Flash attention, split-bf16 mma.sync. TWO q-tiles per CTA (heavy+light =
// uniform 34 k-tiles), base-2 softmax, single barrier/tile, warp diag skip.
// ---------------------------------------------------------------------------
#define AT_SMEM (32768 + 2*32768)
#define SCL2 0.18033688011112042f   /* 0.125 * log2(e) */

__device__ __forceinline__ void at_stage64(uint32_t dst, const __nv_bfloat16* src,
                                           int rowstride, int tid) {
#pragma unroll
    for (int t = 0; t < 2; t++) {
        int idx = tid + t * 256;
        int row = idx >> 3, c16 = idx & 7;
        const void* gp = src + (size_t)row * rowstride + c16 * 8;
        uint32_t sa = dst + (uint32_t)(row * 128 + ((c16 ^ (row & 7)) << 4));
        CPASYNC16(sa, gp);
    }
}

__global__ __launch_bounds__(256, 2) void attn_mma() {
    extern __shared__ __align__(128) char smraw[];
    const uint32_t sb = smem_u32(smraw);
    const int tid = threadIdx.x;
    const int wid = tid >> 5;
    const int lane = tid & 31;
    const int bh = blockIdx.x;
    const int qty = blockIdx.y;               // 0..7

    const size_t qk_off = (size_t)bh * SEQ * HD;
    const size_t vt_off = (size_t)bh * HD * SEQ;
    const int b = bh >> 4, h = bh & 15;

    const int arow_l = ((lane >> 3) & 1) * 8 + (lane & 7);
    const int brow_b = (lane & 7) + (lane >> 4) * 8;
    const int bsel = (lane >> 3) & 1;
    const int asel = lane >> 4;

    for (int pass = 0; pass < 2; pass++) {
        const int qt = pass == 0 ? (15 - qty) : qty;   // heavy tile first
        const int q0 = qt * 128;
        const int nkt = 2 * qt + 2;

        __syncthreads();   // safe smem reuse across passes

        // stage Q (128 rows x 64), hi+lo
#pragma unroll
        for (int t = 0; t < 4; t++) {
            int idx = tid + t * 256;
            int row = idx >> 3, c16 = idx & 7;
            uint32_t sw = (uint32_t)(row * 128 + ((c16 ^ (row & 7)) << 4));
            CPASYNC16(sb + sw, s_qhi + qk_off + (size_t)(q0 + row) * HD + c16 * 8);
            CPASYNC16(sb + 16384u + sw, s_qlo + qk_off + (size_t)(q0 + row) * HD + c16 * 8);
        }
        {
            uint32_t d0 = sb + 32768u;
            at_stage64(d0,           s_khi + qk_off, HD, tid);
            at_stage64(d0 + 8192u,   s_klo + qk_off, HD, tid);
            at_stage64(d0 + 16384u,  s_vthi + vt_off, SEQ, tid);
            at_stage64(d0 + 24576u,  s_vtlo + vt_off, SEQ, tid);
        }
        asm volatile("cp.async.commit_group;" ::: "memory");

        float O[8][4];
#pragma unroll
        for (int nf = 0; nf < 8; nf++)
#pragma unroll
            for (int j = 0; j < 4; j++) O[nf][j] = 0.f;
        float m0 = -1e30f, m1 = -1e30f, l0 = 0.f, l1 = 0.f;

        const int r0g = q0 + wid * 16 + (lane >> 2);
        const int arow = wid * 16 + arow_l;

        for (int kt = 0; kt < nkt; kt++) {
            const int p = kt & 1;
            const int k0 = kt * 64;
            asm volatile("cp.async.wait_group 0;" ::: "memory");
            __syncthreads();
            if (kt + 1 < nkt) {
                uint32_t dn = sb + 32768u + (uint32_t)(p ^ 1) * 32768u;
                int kn = (kt + 1) * 64;
                at_stage64(dn,          s_khi + qk_off + (size_t)kn * HD, HD, tid);
                at_stage64(dn + 8192u,  s_klo + qk_off + (size_t)kn * HD, HD, tid);
                at_stage64(dn + 16384u, s_vthi + vt_off + kn, SEQ, tid);
                at_stage64(dn + 24576u, s_vtlo + vt_off + kn, SEQ, tid);
                asm volatile("cp.async.commit_group;" ::: "memory");
            }

            if (q0 + wid * 16 + 15 < k0) continue;   // fully masked for warp

            const uint32_t kb = sb + 32768u + (uint32_t)p * 32768u;

            float S[8][4];
#pragma unroll
            for (int nf = 0; nf < 8; nf++)
#pragma unroll
                for (int j = 0; j < 4; j++) S[nf][j] = 0.f;
#pragma unroll
            for (int kh = 0; kh < 4; kh++) {
                int ac16 = 2 * kh + asel;
                uint32_t aoff = (uint32_t)(arow * 128 + ((ac16 ^ (arow & 7)) << 4));
                uint32_t qh[4], ql[4];
                LDMX4(qh, sb + aoff);
                LDMX4(ql, sb + 16384u + aoff);
                int bc16 = 2 * kh + bsel;
#pragma unroll
                for (int bp = 0; bp < 4; bp++) {
                    int brow = bp * 16 + brow_b;
                    uint32_t boff = (uint32_t)(brow * 128 + ((bc16 ^ (brow & 7)) << 4));
                    uint32_t th[4], tl[4];
                    LDMX4(th, kb + boff);
                    LDMX4(tl, kb + 8192u + boff);
                    MMA16816(S[2*bp],   qh, th[0], th[1]);
                    MMA16816(S[2*bp+1], qh, th[2], th[3]);
                    MMA16816(S[2*bp],   qh, tl[0], tl[1]);
                    MMA16816(S[2*bp+1], qh, tl[2], tl[3]);
                    MMA16816(S[2*bp],   ql, th[0], th[1]);
                    MMA16816(S[2*bp+1], ql, th[2], th[3]);
                }
            }

            const bool msk = (k0 >= q0);
#pragma unroll
            for (int nf = 0; nf < 8; nf++)
#pragma unroll
                for (int j = 0; j < 4; j++) {
                    float sv = S[nf][j] * SCL2;
                    if (msk) {
                        int col = k0 + nf * 8 + (lane & 3) * 2 + (j & 1);
                        int row = (j < 2) ? r0g : r0g + 8;
                        if (col > row) sv = -1e30f;
                    }
                    S[nf][j] = sv;
                }

            float tm0 = -1e30f, tm1 = -1e30f;
#pragma unroll
            for (int nf = 0; nf < 8; nf++) {
                tm0 = fmaxf(tm0, fmaxf(S[nf][0], S[nf][1]));
                tm1 = fmaxf(tm1, fmaxf(S[nf][2], S[nf][3]));
            }
            tm0 = fmaxf(tm0, __shfl_xor_sync(0xffffffffu, tm0, 1));
            tm0 = fmaxf(tm0, __shfl_xor_sync(0xffffffffu, tm0, 2));
            tm1 = fmaxf(tm1, __shfl_xor_sync(0xffffffffu, tm1, 1));
            tm1 = fmaxf(tm1, __shfl_xor_sync(0xffffffffu, tm1, 2));
            float mn0 = fmaxf(m0, tm0), mn1 = fmaxf(m1, tm1);
            float f0 = exp2f(m0 - mn0), f1 = exp2f(m1 - mn1);
            m0 = mn0; m1 = mn1;
            float rs0 = 0.f, rs1 = 0.f;
#pragma unroll
            for (int nf = 0; nf < 8; nf++) {
                S[nf][0] = exp2f(S[nf][0] - mn0); rs0 += S[nf][0];
                S[nf][1] = exp2f(S[nf][1] - mn0); rs0 += S[nf][1];
                S[nf][2] = exp2f(S[nf][2] - mn1); rs1 += S[nf][2];
                S[nf][3] = exp2f(S[nf][3] - mn1); rs1 += S[nf][3];
            }
            rs0 += __shfl_xor_sync(0xffffffffu, rs0, 1);
            rs0 += __shfl_xor_sync(0xffffffffu, rs0, 2);
            rs1 += __shfl_xor_sync(0xffffffffu, rs1, 1);
            rs1 += __shfl_xor_sync(0xffffffffu, rs1, 2);
            l0 = l0 * f0 + rs0;
            l1 = l1 * f1 + rs1;
#pragma unroll
            for (int nf = 0; nf < 8; nf++) {
                O[nf][0] *= f0; O[nf][1] *= f0;
                O[nf][2] *= f1; O[nf][3] *= f1;
            }

#pragma unroll
            for (int kk = 0; kk < 4; kk++) {
                uint32_t ah[4], al[4];
                split2(S[2*kk][0],   S[2*kk][1],   ah[0], al[0]);
                split2(S[2*kk][2],   S[2*kk][3],   ah[1], al[1]);
                split2(S[2*kk+1][0], S[2*kk+1][1], ah[2], al[2]);
                split2(S[2*kk+1][2], S[2*kk+1][3], ah[3], al[3]);
                int bc16 = 2 * kk + bsel;
#pragma unroll
                for (int bp = 0; bp < 4; bp++) {
                    int brow = bp * 16 + brow_b;
                    uint32_t boff = (uint32_t)(brow * 128 + ((bc16 ^ (brow & 7)) << 4));
                    uint32_t vh[4], vl[4];
                    LDMX4(vh, kb + 16384u + boff);
                    LDMX4(vl, kb + 24576u + boff);
                    MMA16816(O[2*bp],   ah, vh[0], vh[1]);
                    MMA16816(O[2*bp+1], ah, vh[2], vh[3]);
                    MMA16816(O[2*bp],   ah, vl[0], vl[1]);
                    MMA16816(O[2*bp+1], ah, vl[2], vl[3]);
                    MMA16816(O[2*bp],   al, vh[0], vh[1]);
                    MMA16816(O[2*bp+1], al, vh[2], vh[3]);
                }
            }
        }

        // epilogue for this q-tile
        const float inv0 = 1.0f / l0, inv1 = 1.0f / l1;
        const size_t mrow0 = (size_t)(b * SEQ + r0g) * DM;
        const size_t mrow1 = (size_t)(b * SEQ + r0g + 8) * DM;
        const int colb = h * HD + (lane & 3) * 2;
#pragma unroll
        for (int nf = 0; nf < 8; nf++) {
            int col = colb + nf * 8;
            uint32_t hi, lo;
            split2(O[nf][0] * inv0, O[nf][1] * inv0, hi, lo);
            *(uint32_t*)(s_ahi + mrow0 + col) = hi;
            *(uint32_t*)(s_alo + mrow0 + col) = lo;
            split2(O[nf][2] * inv1, O[nf][3] * inv1, hi, lo);
            *(uint32_t*)(s_ahi + mrow1 + col) = hi;
            *(uint32_t*)(s_alo + mrow1 + col) = lo;
        }
    }
}

// ---------------------------------------------------------------------------
extern "C" void kernel_launch(void* const* d_in, const int* in_sizes, int n_in,
                              void* d_out, int out_size) {
    (void)out_size;
    const float* x = (const float*)d_in[0];
    const float* w_qkv = (const float*)d_in[1];
    const float* w_out = (const float*)d_in[2];
    for (int i = 0; i < n_in; i++) {
        if (in_sizes[i] == 8388608)      x     = (const float*)d_in[i];
        else if (in_sizes[i] == 3145728) w_qkv = (const float*)d_in[i];
        else if (in_sizes[i] == 1048576) w_out = (const float*)d_in[i];
    }
    float* out = (float*)d_out;

    void *p_xhi, *p_xlo, *p_whi, *p_wlo, *p_ohi, *p_olo, *p_ahi, *p_alo;
    cudaGetSymbolAddress(&p_xhi, s_xhi);
    cudaGetSymbolAddress(&p_xlo, s_xlo);
    cudaGetSymbolAddress(&p_whi, s_whi);
    cudaGetSymbolAddress(&p_wlo, s_wlo);
    cudaGetSymbolAddress(&p_ohi, s_ohi);
    cudaGetSymbolAddress(&p_olo, s_olo);
    cudaGetSymbolAddress(&p_ahi, s_ahi);
    cudaGetSymbolAddress(&p_alo, s_alo);

    cudaFuncSetAttribute(gemm_mma, cudaFuncAttributeMaxDynamicSharedMemorySize, GEMM_SMEM);
    cudaFuncSetAttribute(attn_mma, cudaFuncAttributeMaxDynamicSharedMemorySize, AT_SMEM);

    cvt_split3<<<(N_X + N_W + N_O) / 1024, 256>>>(x, w_qkv, w_out);

    gemm_mma<<<dim3(3*DM/128, MTOT/128), 256, GEMM_SMEM>>>(
        (const __nv_bfloat16*)p_xhi, (const __nv_bfloat16*)p_xlo,
        (const __nv_bfloat16*)p_whi, (const __nv_bfloat16*)p_wlo, nullptr, 1);

    transpose_v<<<dim3(BATCH*NH, SEQ/64), 256>>>();

    attn_mma<<<dim3(BATCH*NH, 8), 256, AT_SMEM>>>();

    gemm_mma<<<dim3(DM/128, MTOT/128), 256, GEMM_SMEM>>>(
        (const __nv_bfloat16*)p_ahi, (const __nv_bfloat16*)p_alo,
        (const __nv_bfloat16*)p_ohi, (const __nv_bfloat16*)p_olo, out, 0);
}

// round 15
// speedup vs baseline: 1.0621x; 1.0621x over previous
#include <cuda_runtime.h>
#include <cuda_bf16.h>
#include <math.h>
#include <stdint.h>

#define BATCH 4
#define SEQ   2048
#define DM    1024
#define NH    16
#define HD    64
#define MTOT  (BATCH*SEQ)   // 8192

// ---------------- scratch (__device__ statics; allocation-guard safe) -------
__device__ float g_v[(size_t)BATCH*NH*SEQ*HD];

__device__ __nv_bfloat16 s_xhi[(size_t)MTOT*DM];
__device__ __nv_bfloat16 s_xlo[(size_t)MTOT*DM];
__device__ __nv_bfloat16 s_whi[(size_t)3*DM*DM];
__device__ __nv_bfloat16 s_wlo[(size_t)3*DM*DM];
__device__ __nv_bfloat16 s_ohi[(size_t)DM*DM];
__device__ __nv_bfloat16 s_olo[(size_t)DM*DM];
__device__ __nv_bfloat16 s_ahi[(size_t)MTOT*DM];
__device__ __nv_bfloat16 s_alo[(size_t)MTOT*DM];

__device__ __nv_bfloat16 s_qhi[(size_t)BATCH*NH*SEQ*HD];
__device__ __nv_bfloat16 s_qlo[(size_t)BATCH*NH*SEQ*HD];
__device__ __nv_bfloat16 s_khi[(size_t)BATCH*NH*SEQ*HD];
__device__ __nv_bfloat16 s_klo[(size_t)BATCH*NH*SEQ*HD];
__device__ __nv_bfloat16 s_vthi[(size_t)BATCH*NH*HD*SEQ];  // [bh][d][s]
__device__ __nv_bfloat16 s_vtlo[(size_t)BATCH*NH*HD*SEQ];

// ---------------- helpers ----------------------------------------------------
__device__ __forceinline__ uint32_t smem_u32(const void* p) {
    uint32_t a;
    asm("{ .reg .u64 t; cvta.to.shared.u64 t, %1; cvt.u32.u64 %0, t; }"
        : "=r"(a) : "l"(p));
    return a;
}
#define LDMX4(d, a) \
    asm volatile("ldmatrix.sync.aligned.m8n8.x4.shared.b16 {%0,%1,%2,%3}, [%4];" \
                 : "=r"((d)[0]), "=r"((d)[1]), "=r"((d)[2]), "=r"((d)[3]) : "r"(a))
#define MMA16816(c, a, b0, b1) \
    asm volatile("mma.sync.aligned.m16n8k16.row.col.f32.bf16.bf16.f32 " \
                 "{%0,%1,%2,%3}, {%4,%5,%6,%7}, {%8,%9}, {%0,%1,%2,%3};" \
                 : "+f"((c)[0]), "+f"((c)[1]), "+f"((c)[2]), "+f"((c)[3]) \
                 : "r"((a)[0]), "r"((a)[1]), "r"((a)[2]), "r"((a)[3]), \
                   "r"(b0), "r"(b1))
#define CPASYNC16(sa, gp) \
    asm volatile("cp.async.cg.shared.global [%0], [%1], 16;" :: "r"(sa), "l"(gp))

__device__ __forceinline__ uint32_t pack_bf2(float a, float b) {
    __nv_bfloat162 t;
    t.x = __float2bfloat16(a);
    t.y = __float2bfloat16(b);
    return *reinterpret_cast<uint32_t*>(&t);
}
__device__ __forceinline__ void split2(float a, float b, uint32_t& hi, uint32_t& lo) {
    __nv_bfloat16 ah = __float2bfloat16(a), bh = __float2bfloat16(b);
    __nv_bfloat162 h; h.x = ah; h.y = bh;
    hi = *reinterpret_cast<uint32_t*>(&h);
    lo = pack_bf2(a - __bfloat162float(ah), b - __bfloat162float(bh));
}

// ---------------------------------------------------------------------------
// fp32 -> bf16 hi/lo split of all three inputs, ONE launch, float4 vectorized
// ---------------------------------------------------------------------------
#define N_X (MTOT*DM)        // 8388608
#define N_W (3*DM*DM)        // 3145728
#define N_O (DM*DM)          // 1048576

__global__ __launch_bounds__(256) void cvt_split3(
    const float* __restrict__ x, const float* __restrict__ wq,
    const float* __restrict__ wo)
{
    int i4 = blockIdx.x * 256 + threadIdx.x;   // float4 index
    int i = i4 * 4;
    const float* src;
    __nv_bfloat16 *hi, *lo;
    int j;
    if (i < N_X)              { src = x;  hi = s_xhi; lo = s_xlo; j = i; }
    else if (i < N_X + N_W)   { src = wq; hi = s_whi; lo = s_wlo; j = i - N_X; }
    else                      { src = wo; hi = s_ohi; lo = s_olo; j = i - N_X - N_W; }
    float4 v = *(const float4*)(src + j);
    uint32_t h0, l0, h1, l1;
    split2(v.x, v.y, h0, l0);
    split2(v.z, v.w, h1, l1);
    *(uint2*)(hi + j) = make_uint2(h0, h1);
    *(uint2*)(lo + j) = make_uint2(l0, l1);
}

// ---------------------------------------------------------------------------
// Split-bf16 tensor-core GEMM (frozen r13). 2-stage, one barrier per chunk.
// mode 0: OUT store. mode 1: q/k -> RoPE+split; v -> g_v fp32.
// ---------------------------------------------------------------------------
#define GEMM_SMEM 65536

__device__ __forceinline__ void stage_chunk(
    uint32_t smbase, int p, int c,
    const __nv_bfloat16* s0, const __nv_bfloat16* s1,
    const __nv_bfloat16* s2, const __nv_bfloat16* s3, int tid)
{
    const __nv_bfloat16* srcs[4] = {s0, s1, s2, s3};
    const uint32_t bufb = smbase + (uint32_t)p * 32768u;
#pragma unroll
    for (int comp = 0; comp < 4; comp++) {
        const __nv_bfloat16* s = srcs[comp] + c * 32;
        const uint32_t db = bufb + (uint32_t)comp * 8192u;
#pragma unroll
        for (int t = 0; t < 2; t++) {
            int idx = tid + t * 256;
            int row = idx >> 2, c16 = idx & 3;
            const void* gp = s + (size_t)row * DM + c16 * 8;
            uint32_t sw = db + (uint32_t)(row * 64)
                        + ((uint32_t)(c16 ^ ((row >> 1) & 3)) << 4);
            CPASYNC16(sw, gp);
        }
    }
    asm volatile("cp.async.commit_group;" ::: "memory");
}

__global__ __launch_bounds__(256, 2) void gemm_mma(
    const __nv_bfloat16* __restrict__ Ahi, const __nv_bfloat16* __restrict__ Alo,
    const __nv_bfloat16* __restrict__ Bhi, const __nv_bfloat16* __restrict__ Blo,
    float* __restrict__ OUT, int mode)
{
    extern __shared__ __align__(128) char smraw[];
    const uint32_t smbase = smem_u32(smraw);
    const int tid  = threadIdx.x;
    const int wid  = tid >> 5;
    const int lane = tid & 31;
    const int wm   = wid >> 2;
    const int wn   = wid & 3;
    const int n0   = blockIdx.x * 128;
    const int m0   = blockIdx.y * 128;

    const __nv_bfloat16* gAhi = Ahi + (size_t)m0 * DM;
    const __nv_bfloat16* gAlo = Alo + (size_t)m0 * DM;
    const __nv_bfloat16* gBhi = Bhi + (size_t)n0 * DM;
    const __nv_bfloat16* gBlo = Blo + (size_t)n0 * DM;

    float C[4][4][4];
#pragma unroll
    for (int i = 0; i < 4; i++)
#pragma unroll
        for (int j = 0; j < 4; j++)
#pragma unroll
            for (int k = 0; k < 4; k++) C[i][j][k] = 0.f;

    const int g = lane >> 3, r = lane & 7;

    stage_chunk(smbase, 0, 0, gAhi, gAlo, gBhi, gBlo, tid);

    for (int c = 0; c < 32; c++) {
        const int p = c & 1;
        asm volatile("cp.async.wait_group 0;" ::: "memory");
        __syncthreads();
        if (c + 1 < 32)
            stage_chunk(smbase, p ^ 1, c + 1, gAhi, gAlo, gBhi, gBlo, tid);

        const uint32_t ab = smbase + (uint32_t)p * 32768u;
#pragma unroll
        for (int kh = 0; kh < 2; kh++) {
            const int kkc = kh * 2;
            uint32_t bhi[4][2], blo[4][2];
#pragma unroll
            for (int bp = 0; bp < 2; bp++) {
                int row = wn * 32 + bp * 16 + (g >> 1) * 8 + r;
                int c16 = kkc + (g & 1);
                uint32_t sw = (uint32_t)(row * 64)
                            + ((uint32_t)(c16 ^ ((row >> 1) & 3)) << 4);
                uint32_t t[4];
                LDMX4(t, ab + 16384u + sw);
                bhi[bp*2][0] = t[0]; bhi[bp*2][1] = t[1];
                bhi[bp*2+1][0] = t[2]; bhi[bp*2+1][1] = t[3];
                LDMX4(t, ab + 24576u + sw);
                blo[bp*2][0] = t[0]; blo[bp*2][1] = t[1];
                blo[bp*2+1][0] = t[2]; blo[bp*2+1][1] = t[3];
            }
#pragma unroll
            for (int mf = 0; mf < 4; mf++) {
                int row = wm * 64 + mf * 16 + (g & 1) * 8 + r;
                int c16 = kkc + (g >> 1);
                uint32_t sw = (uint32_t)(row * 64)
                            + ((uint32_t)(c16 ^ ((row >> 1) & 3)) << 4);
                uint32_t ah[4], al[4];
                LDMX4(ah, ab + sw);
                LDMX4(al, ab + 8192u + sw);
#pragma unroll
                for (int nf = 0; nf < 4; nf++) {
                    MMA16816(C[mf][nf], ah, bhi[nf][0], bhi[nf][1]);
                    MMA16816(C[mf][nf], ah, blo[nf][0], blo[nf][1]);
                    MMA16816(C[mf][nf], al, bhi[nf][0], bhi[nf][1]);
                }
            }
        }
    }

    // ---------------- epilogue ----------------
#pragma unroll
    for (int mf = 0; mf < 4; mf++) {
#pragma unroll
        for (int nf = 0; nf < 4; nf++) {
            int row0 = m0 + wm * 64 + mf * 16 + (lane >> 2);
            int col  = n0 + wn * 32 + nf * 8 + (lane & 3) * 2;   // even
            if (mode == 0) {
                *(float2*)(OUT + (size_t)row0 * DM + col) =
                    make_float2(C[mf][nf][0], C[mf][nf][1]);
                *(float2*)(OUT + (size_t)(row0 + 8) * DM + col) =
                    make_float2(C[mf][nf][2], C[mf][nf][3]);
            } else {
                const int which = col >> 10;
                const int h  = (col & 1023) >> 6;
                const int dd = col & 63;
                if (which == 2) {
#pragma unroll
                    for (int rr = 0; rr < 2; rr++) {
                        int row = row0 + rr * 8;
                        int b = row >> 11, s = row & 2047;
                        float* vp = g_v + (((size_t)(b * NH + h) * SEQ + s) * HD) + dd;
                        *(float2*)vp = make_float2(C[mf][nf][2*rr], C[mf][nf][2*rr+1]);
                    }
                } else {
                    // Q/K: RoPE (neg-sin interleaved, validated r6) + split
                    __nv_bfloat16* dhi = (which == 0) ? s_qhi : s_khi;
                    __nv_bfloat16* dlo = (which == 0) ? s_qlo : s_klo;
                    const float inv_f = expf((float)dd * -0.14391156831212787f);
#pragma unroll
                    for (int rr = 0; rr < 2; rr++) {
                        int row = row0 + rr * 8;
                        int b = row >> 11, s = row & 2047;
                        float cs, sn;
                        sincosf((float)s * inv_f, &cs, &sn);
                        float x0 = C[mf][nf][2*rr], x1 = C[mf][nf][2*rr+1];
                        float y0 = x0 * cs + x1 * sn;
                        float y1 = x1 * cs - x0 * sn;
                        uint32_t hi, lo;
                        split2(y0, y1, hi, lo);
                        size_t off = (((size_t)(b * NH + h) * SEQ + s) * HD) + dd;
                        *(uint32_t*)(dhi + off) = hi;
                        *(uint32_t*)(dlo + off) = lo;
                    }
                }
            }
        }
    }
}

// ---------------------------------------------------------------------------
// V transpose + split: g_v fp32 [bh][s][d] -> s_vthi/s_vtlo [bh][d][s]
// ---------------------------------------------------------------------------
__global__ __launch_bounds__(256) void transpose_v() {
    __shared__ float t[64][65];
    const int bh = blockIdx.x, s0 = blockIdx.y * 64;
    const int tid = threadIdx.x;
    const float* src = g_v + (size_t)bh * SEQ * HD + (size_t)s0 * HD;
#pragma unroll
    for (int i = 0; i < 4; i++) {
        int idx = tid + i * 256;
        int rr = idx >> 4, cc = (idx & 15) << 2;
        float4 v = *(const float4*)(src + rr * HD + cc);
        t[rr][cc] = v.x; t[rr][cc+1] = v.y; t[rr][cc+2] = v.z; t[rr][cc+3] = v.w;
    }
    __syncthreads();
    __nv_bfloat16* dhi = s_vthi + (size_t)bh * HD * SEQ + s0;
    __nv_bfloat16* dlo = s_vtlo + (size_t)bh * HD * SEQ + s0;
#pragma unroll
    for (int i = 0; i < 8; i++) {
        int idx = tid + i * 256;
        int d = idx >> 5, sp = (idx & 31) << 1;
        uint32_t hi, lo;
        split2(t[sp][d], t[sp+1][d], hi, lo);
        *(uint32_t*)(dhi + (size_t)d * SEQ + sp) = hi;
        *(uint32_t*)(dlo + (size_t)d * SEQ + sp) = lo;
    }
}

// ---------------------------------------------------------------------------
// Flash attention, split-bf16 mma.sync (exact r13 form: 1024 CTAs heavy-first,
// base-2 softmax, single barrier/tile, warp-level diagonal skip).
// ---------------------------------------------------------------------------
#define AT_SMEM (32768 + 2*32768)
#define SCL2 0.18033688011112042f   /* 0.125 * log2(e) */

__device__ __forceinline__ void at_stage64(uint32_t dst, const __nv_bfloat16* src,
                                           int rowstride, int tid) {
#pragma unroll
    for (int t = 0; t < 2; t++) {
        int idx = tid + t * 256;
        int row = idx >> 3, c16 = idx & 7;
        const void* gp = src + (size_t)row * rowstride + c16 * 8;
        uint32_t sa = dst + (uint32_t)(row * 128 + ((c16 ^ (row & 7)) << 4));
        CPASYNC16(sa, gp);
    }
}

__global__ __launch_bounds__(256, 2) void attn_mma() {
    extern __shared__ __align__(128) char smraw[];
    const uint32_t sb = smem_u32(smraw);
    const int tid = threadIdx.x;
    const int wid = tid >> 5;
    const int lane = tid & 31;
    const int bh = blockIdx.x;
    const int qt = 15 - blockIdx.y;           // heavy tiles first
    const int q0 = qt * 128;
    const int nkt = 2 * qt + 2;

    const size_t qk_off = (size_t)bh * SEQ * HD;
    const size_t vt_off = (size_t)bh * HD * SEQ;

#pragma unroll
    for (int t = 0; t < 4; t++) {
        int idx = tid + t * 256;
        int row = idx >> 3, c16 = idx & 7;
        uint32_t sw = (uint32_t)(row * 128 + ((c16 ^ (row & 7)) << 4));
        CPASYNC16(sb + sw, s_qhi + qk_off + (size_t)(q0 + row) * HD + c16 * 8);
        CPASYNC16(sb + 16384u + sw, s_qlo + qk_off + (size_t)(q0 + row) * HD + c16 * 8);
    }
    {
        uint32_t d0 = sb + 32768u;
        at_stage64(d0,           s_khi + qk_off, HD, tid);
        at_stage64(d0 + 8192u,   s_klo + qk_off, HD, tid);
        at_stage64(d0 + 16384u,  s_vthi + vt_off, SEQ, tid);
        at_stage64(d0 + 24576u,  s_vtlo + vt_off, SEQ, tid);
    }
    asm volatile("cp.async.commit_group;" ::: "memory");

    float O[8][4];
#pragma unroll
    for (int nf = 0; nf < 8; nf++)
#pragma unroll
        for (int j = 0; j < 4; j++) O[nf][j] = 0.f;
    float m0 = -1e30f, m1 = -1e30f, l0 = 0.f, l1 = 0.f;

    const int r0g = q0 + wid * 16 + (lane >> 2);
    const int arow = wid * 16 + ((lane >> 3) & 1) * 8 + (lane & 7);
    const int brow_b = (lane & 7) + (lane >> 4) * 8;
    const int bsel = (lane >> 3) & 1;
    const int asel = lane >> 4;

    for (int kt = 0; kt < nkt; kt++) {
        const int p = kt & 1;
        const int k0 = kt * 64;
        asm volatile("cp.async.wait_group 0;" ::: "memory");
        __syncthreads();
        if (kt + 1 < nkt) {
            uint32_t dn = sb + 32768u + (uint32_t)(p ^ 1) * 32768u;
            int kn = (kt + 1) * 64;
            at_stage64(dn,          s_khi + qk_off + (size_t)kn * HD, HD, tid);
            at_stage64(dn + 8192u,  s_klo + qk_off + (size_t)kn * HD, HD, tid);
            at_stage64(dn + 16384u, s_vthi + vt_off + kn, SEQ, tid);
            at_stage64(dn + 24576u, s_vtlo + vt_off + kn, SEQ, tid);
            asm volatile("cp.async.commit_group;" ::: "memory");
        }

        if (q0 + wid * 16 + 15 < k0) continue;   // fully masked for this warp

        const uint32_t kb = sb + 32768u + (uint32_t)p * 32768u;

        float S[8][4];
#pragma unroll
        for (int nf = 0; nf < 8; nf++)
#pragma unroll
            for (int j = 0; j < 4; j++) S[nf][j] = 0.f;
#pragma unroll
        for (int kh = 0; kh < 4; kh++) {
            int ac16 = 2 * kh + asel;
            uint32_t aoff = (uint32_t)(arow * 128 + ((ac16 ^ (arow & 7)) << 4));
            uint32_t qh[4], ql[4];
            LDMX4(qh, sb + aoff);
            LDMX4(ql, sb + 16384u + aoff);
            int bc16 = 2 * kh + bsel;
#pragma unroll
            for (int bp = 0; bp < 4; bp++) {
                int brow = bp * 16 + brow_b;
                uint32_t boff = (uint32_t)(brow * 128 + ((bc16 ^ (brow & 7)) << 4));
                uint32_t th[4], tl[4];
                LDMX4(th, kb + boff);
                LDMX4(tl, kb + 8192u + boff);
                MMA16816(S[2*bp],   qh, th[0], th[1]);
                MMA16816(S[2*bp+1], qh, th[2], th[3]);
                MMA16816(S[2*bp],   qh, tl[0], tl[1]);
                MMA16816(S[2*bp+1], qh, tl[2], tl[3]);
                MMA16816(S[2*bp],   ql, th[0], th[1]);
                MMA16816(S[2*bp+1], ql, th[2], th[3]);
            }
        }

        // scale into base-2 domain + causal mask
        const bool msk = (k0 >= q0);
#pragma unroll
        for (int nf = 0; nf < 8; nf++)
#pragma unroll
            for (int j = 0; j < 4; j++) {
                float sv = S[nf][j] * SCL2;
                if (msk) {
                    int col = k0 + nf * 8 + (lane & 3) * 2 + (j & 1);
                    int row = (j < 2) ? r0g : r0g + 8;
                    if (col > row) sv = -1e30f;
                }
                S[nf][j] = sv;
            }

        float tm0 = -1e30f, tm1 = -1e30f;
#pragma unroll
        for (int nf = 0; nf < 8; nf++) {
            tm0 = fmaxf(tm0, fmaxf(S[nf][0], S[nf][1]));
            tm1 = fmaxf(tm1, fmaxf(S[nf][2], S[nf][3]));
        }
        tm0 = fmaxf(tm0, __shfl_xor_sync(0xffffffffu, tm0, 1));
        tm0 = fmaxf(tm0, __shfl_xor_sync(0xffffffffu, tm0, 2));
        tm1 = fmaxf(tm1, __shfl_xor_sync(0xffffffffu, tm1, 1));
        tm1 = fmaxf(tm1, __shfl_xor_sync(0xffffffffu, tm1, 2));
        float mn0 = fmaxf(m0, tm0), mn1 = fmaxf(m1, tm1);
        float f0 = exp2f(m0 - mn0), f1 = exp2f(m1 - mn1);
        m0 = mn0; m1 = mn1;
        float rs0 = 0.f, rs1 = 0.f;
#pragma unroll
        for (int nf = 0; nf < 8; nf++) {
            S[nf][0] = exp2f(S[nf][0] - mn0); rs0 += S[nf][0];
            S[nf][1] = exp2f(S[nf][1] - mn0); rs0 += S[nf][1];
            S[nf][2] = exp2f(S[nf][2] - mn1); rs1 += S[nf][2];
            S[nf][3] = exp2f(S[nf][3] - mn1); rs1 += S[nf][3];
        }
        rs0 += __shfl_xor_sync(0xffffffffu, rs0, 1);
        rs0 += __shfl_xor_sync(0xffffffffu, rs0, 2);
        rs1 += __shfl_xor_sync(0xffffffffu, rs1, 1);
        rs1 += __shfl_xor_sync(0xffffffffu, rs1, 2);
        l0 = l0 * f0 + rs0;
        l1 = l1 * f1 + rs1;
#pragma unroll
        for (int nf = 0; nf < 8; nf++) {
            O[nf][0] *= f0; O[nf][1] *= f0;
            O[nf][2] *= f1; O[nf][3] *= f1;
        }

#pragma unroll
        for (int kk = 0; kk < 4; kk++) {
            uint32_t ah[4], al[4];
            split2(S[2*kk][0],   S[2*kk][1],   ah[0], al[0]);
            split2(S[2*kk][2],   S[2*kk][3],   ah[1], al[1]);
            split2(S[2*kk+1][0], S[2*kk+1][1], ah[2], al[2]);
            split2(S[2*kk+1][2], S[2*kk+1][3], ah[3], al[3]);
            int bc16 = 2 * kk + bsel;
#pragma unroll
            for (int bp = 0; bp < 4; bp++) {
                int brow = bp * 16 + brow_b;
                uint32_t boff = (uint32_t)(brow * 128 + ((bc16 ^ (brow & 7)) << 4));
                uint32_t vh[4], vl[4];
                LDMX4(vh, kb + 16384u + boff);
                LDMX4(vl, kb + 24576u + boff);
                MMA16816(O[2*bp],   ah, vh[0], vh[1]);
                MMA16816(O[2*bp+1], ah, vh[2], vh[3]);
                MMA16816(O[2*bp],   ah, vl[0], vl[1]);
                MMA16816(O[2*bp+1], ah, vl[2], vl[3]);
                MMA16816(O[2*bp],   al, vh[0], vh[1]);
                MMA16816(O[2*bp+1], al, vh[2], vh[3]);
            }
        }
    }

    const int b = bh >> 4, h = bh & 15;
    const float inv0 = 1.0f / l0, inv1 = 1.0f / l1;
    const size_t mrow0 = (size_t)(b * SEQ + r0g) * DM;
    const size_t mrow1 = (size_t)(b * SEQ + r0g + 8) * DM;
    const int colb = h * HD + (lane & 3) * 2;
#pragma unroll
    for (int nf = 0; nf < 8; nf++) {
        int col = colb + nf * 8;
        uint32_t hi, lo;
        split2(O[nf][0] * inv0, O[nf][1] * inv0, hi, lo);
        *(uint32_t*)(s_ahi + mrow0 + col) = hi;
        *(uint32_t*)(s_alo + mrow0 + col) = lo;
        split2(O[nf][2] * inv1, O[nf][3] * inv1, hi, lo);
        *(uint32_t*)(s_ahi + mrow1 + col) = hi;
        *(uint32_t*)(s_alo + mrow1 + col) = lo;
    }
}

// ---------------------------------------------------------------------------
extern "C" void kernel_launch(void* const* d_in, const int* in_sizes, int n_in,
                              void* d_out, int out_size) {
    (void)out_size;
    const float* x = (const float*)d_in[0];
    const float* w_qkv = (const float*)d_in[1];
    const float* w_out = (const float*)d_in[2];
    for (int i = 0; i < n_in; i++) {
        if (in_sizes[i] == 8388608)      x     = (const float*)d_in[i];
        else if (in_sizes[i] == 3145728) w_qkv = (const float*)d_in[i];
        else if (in_sizes[i] == 1048576) w_out = (const float*)d_in[i];
    }
    float* out = (float*)d_out;

    void *p_xhi, *p_xlo, *p_whi, *p_wlo, *p_ohi, *p_olo, *p_ahi, *p_alo;
    cudaGetSymbolAddress(&p_xhi, s_xhi);
    cudaGetSymbolAddress(&p_xlo, s_xlo);
    cudaGetSymbolAddress(&p_whi, s_whi);
    cudaGetSymbolAddress(&p_wlo, s_wlo);
    cudaGetSymbolAddress(&p_ohi, s_ohi);
    cudaGetSymbolAddress(&p_olo, s_olo);
    cudaGetSymbolAddress(&p_ahi, s_ahi);
    cudaGetSymbolAddress(&p_alo, s_alo);

    cudaFuncSetAttribute(gemm_mma, cudaFuncAttributeMaxDynamicSharedMemorySize, GEMM_SMEM);
    cudaFuncSetAttribute(attn_mma, cudaFuncAttributeMaxDynamicSharedMemorySize, AT_SMEM);

    cvt_split3<<<(N_X + N_W + N_O) / 1024, 256>>>(x, w_qkv, w_out);

    gemm_mma<<<dim3(3*DM/128, MTOT/128), 256, GEMM_SMEM>>>(
        (const __nv_bfloat16*)p_xhi, (const __nv_bfloat16*)p_xlo,
        (const __nv_bfloat16*)p_whi, (const __nv_bfloat16*)p_wlo, nullptr, 1);

    transpose_v<<<dim3(BATCH*NH, SEQ/64), 256>>>();

    attn_mma<<<dim3(BATCH*NH, SEQ/128), 256, AT_SMEM>>>();

    gemm_mma<<<dim3(DM/128, MTOT/128), 256, GEMM_SMEM>>>(
        (const __nv_bfloat16*)p_ahi, (const __nv_bfloat16*)p_alo,
        (const __nv_bfloat16*)p_ohi, (const __nv_bfloat16*)p_olo, out, 0);
}

// round 16
// speedup vs baseline: 1.1213x; 1.0557x over previous
#include <cuda_runtime.h>
#include <cuda_fp16.h>
#include <math.h>
#include <stdint.h>

#define BATCH 4
#define SEQ   2048
#define DM    1024
#define NH    16
#define HD    64
#define MTOT  (BATCH*SEQ)   // 8192

// ---------------- scratch (__device__ statics; allocation-guard safe) -------
__device__ float g_v[(size_t)BATCH*NH*SEQ*HD];

__device__ __half s_xhi[(size_t)MTOT*DM];
__device__ __half s_xlo[(size_t)MTOT*DM];
__device__ __half s_whi[(size_t)3*DM*DM];
__device__ __half s_wlo[(size_t)3*DM*DM];
__device__ __half s_ohi[(size_t)DM*DM];
__device__ __half s_olo[(size_t)DM*DM];
__device__ __half s_ahi[(size_t)MTOT*DM];
__device__ __half s_alo[(size_t)MTOT*DM];

__device__ __half s_qhi[(size_t)BATCH*NH*SEQ*HD];
__device__ __half s_qlo[(size_t)BATCH*NH*SEQ*HD];
__device__ __half s_khi[(size_t)BATCH*NH*SEQ*HD];
__device__ __half s_klo[(size_t)BATCH*NH*SEQ*HD];
__device__ __half s_vthi[(size_t)BATCH*NH*HD*SEQ];  // [bh][d][s]
__device__ __half s_vtlo[(size_t)BATCH*NH*HD*SEQ];

// ---------------- helpers ----------------------------------------------------
__device__ __forceinline__ uint32_t smem_u32(const void* p) {
    uint32_t a;
    asm("{ .reg .u64 t; cvta.to.shared.u64 t, %1; cvt.u32.u64 %0, t; }"
        : "=r"(a) : "l"(p));
    return a;
}
#define LDMX4(d, a) \
    asm volatile("ldmatrix.sync.aligned.m8n8.x4.shared.b16 {%0,%1,%2,%3}, [%4];" \
                 : "=r"((d)[0]), "=r"((d)[1]), "=r"((d)[2]), "=r"((d)[3]) : "r"(a))
#define MMA16816(c, a, b0, b1) \
    asm volatile("mma.sync.aligned.m16n8k16.row.col.f32.f16.f16.f32 " \
                 "{%0,%1,%2,%3}, {%4,%5,%6,%7}, {%8,%9}, {%0,%1,%2,%3};" \
                 : "+f"((c)[0]), "+f"((c)[1]), "+f"((c)[2]), "+f"((c)[3]) \
                 : "r"((a)[0]), "r"((a)[1]), "r"((a)[2]), "r"((a)[3]), \
                   "r"(b0), "r"(b1))
#define CPASYNC16(sa, gp) \
    asm volatile("cp.async.cg.shared.global [%0], [%1], 16;" :: "r"(sa), "l"(gp))

__device__ __forceinline__ uint32_t pack_h2(float a, float b) {
    __half2 t = __floats2half2_rn(a, b);
    return *reinterpret_cast<uint32_t*>(&t);
}
__device__ __forceinline__ void split2(float a, float b, uint32_t& hi, uint32_t& lo) {
    __half ah = __float2half_rn(a), bh = __float2half_rn(b);
    __half2 h = __halves2half2(ah, bh);
    hi = *reinterpret_cast<uint32_t*>(&h);
    lo = pack_h2(a - __half2float(ah), b - __half2float(bh));
}

// ---------------------------------------------------------------------------
// fp32 -> fp16 hi/lo split of all three inputs, ONE launch, float4 vectorized
// ---------------------------------------------------------------------------
#define N_X (MTOT*DM)        // 8388608
#define N_W (3*DM*DM)        // 3145728
#define N_O (DM*DM)          // 1048576

__global__ __launch_bounds__(256) void cvt_split3(
    const float* __restrict__ x, const float* __restrict__ wq,
    const float* __restrict__ wo)
{
    int i4 = blockIdx.x * 256 + threadIdx.x;   // float4 index
    int i = i4 * 4;
    const float* src;
    __half *hi, *lo;
    int j;
    if (i < N_X)              { src = x;  hi = s_xhi; lo = s_xlo; j = i; }
    else if (i < N_X + N_W)   { src = wq; hi = s_whi; lo = s_wlo; j = i - N_X; }
    else                      { src = wo; hi = s_ohi; lo = s_olo; j = i - N_X - N_W; }
    float4 v = *(const float4*)(src + j);
    uint32_t h0, l0, h1, l1;
    split2(v.x, v.y, h0, l0);
    split2(v.z, v.w, h1, l1);
    *(uint2*)(hi + j) = make_uint2(h0, h1);
    *(uint2*)(lo + j) = make_uint2(l0, l1);
}

// ---------------------------------------------------------------------------
// Split-fp16 tensor-core GEMM. 2-stage, one barrier per chunk.
// mode 0: OUT store, 2-product (drop Al*Bh; A = attn output, linear path).
// mode 1: 3-product; q/k -> RoPE+split; v -> g_v fp32.
// ---------------------------------------------------------------------------
#define GEMM_SMEM 65536

__device__ __forceinline__ void stage_chunk(
    uint32_t smbase, int p, int c,
    const __half* s0, const __half* s1,
    const __half* s2, const __half* s3, int tid)
{
    const __half* srcs[4] = {s0, s1, s2, s3};
    const uint32_t bufb = smbase + (uint32_t)p * 32768u;
#pragma unroll
    for (int comp = 0; comp < 4; comp++) {
        const __half* s = srcs[comp] + c * 32;
        const uint32_t db = bufb + (uint32_t)comp * 8192u;
#pragma unroll
        for (int t = 0; t < 2; t++) {
            int idx = tid + t * 256;
            int row = idx >> 2, c16 = idx & 3;
            const void* gp = s + (size_t)row * DM + c16 * 8;
            uint32_t sw = db + (uint32_t)(row * 64)
                        + ((uint32_t)(c16 ^ ((row >> 1) & 3)) << 4);
            CPASYNC16(sw, gp);
        }
    }
    asm volatile("cp.async.commit_group;" ::: "memory");
}

__global__ __launch_bounds__(256, 2) void gemm_mma(
    const __half* __restrict__ Ahi, const __half* __restrict__ Alo,
    const __half* __restrict__ Bhi, const __half* __restrict__ Blo,
    float* __restrict__ OUT, int mode)
{
    extern __shared__ __align__(128) char smraw[];
    const uint32_t smbase = smem_u32(smraw);
    const int tid  = threadIdx.x;
    const int wid  = tid >> 5;
    const int lane = tid & 31;
    const int wm   = wid >> 2;
    const int wn   = wid & 3;
    const int n0   = blockIdx.x * 128;
    const int m0   = blockIdx.y * 128;
    const bool three = (mode != 0);

    const __half* gAhi = Ahi + (size_t)m0 * DM;
    const __half* gAlo = Alo + (size_t)m0 * DM;
    const __half* gBhi = Bhi + (size_t)n0 * DM;
    const __half* gBlo = Blo + (size_t)n0 * DM;

    float C[4][4][4];
#pragma unroll
    for (int i = 0; i < 4; i++)
#pragma unroll
        for (int j = 0; j < 4; j++)
#pragma unroll
            for (int k = 0; k < 4; k++) C[i][j][k] = 0.f;

    const int g = lane >> 3, r = lane & 7;

    stage_chunk(smbase, 0, 0, gAhi, gAlo, gBhi, gBlo, tid);

    for (int c = 0; c < 32; c++) {
        const int p = c & 1;
        asm volatile("cp.async.wait_group 0;" ::: "memory");
        __syncthreads();
        if (c + 1 < 32)
            stage_chunk(smbase, p ^ 1, c + 1, gAhi, gAlo, gBhi, gBlo, tid);

        const uint32_t ab = smbase + (uint32_t)p * 32768u;
#pragma unroll
        for (int kh = 0; kh < 2; kh++) {
            const int kkc = kh * 2;
            uint32_t bhi[4][2], blo[4][2];
#pragma unroll
            for (int bp = 0; bp < 2; bp++) {
                int row = wn * 32 + bp * 16 + (g >> 1) * 8 + r;
                int c16 = kkc + (g & 1);
                uint32_t sw = (uint32_t)(row * 64)
                            + ((uint32_t)(c16 ^ ((row >> 1) & 3)) << 4);
                uint32_t t[4];
                LDMX4(t, ab + 16384u + sw);
                bhi[bp*2][0] = t[0]; bhi[bp*2][1] = t[1];
                bhi[bp*2+1][0] = t[2]; bhi[bp*2+1][1] = t[3];
                LDMX4(t, ab + 24576u + sw);
                blo[bp*2][0] = t[0]; blo[bp*2][1] = t[1];
                blo[bp*2+1][0] = t[2]; blo[bp*2+1][1] = t[3];
            }
#pragma unroll
            for (int mf = 0; mf < 4; mf++) {
                int row = wm * 64 + mf * 16 + (g & 1) * 8 + r;
                int c16 = kkc + (g >> 1);
                uint32_t sw = (uint32_t)(row * 64)
                            + ((uint32_t)(c16 ^ ((row >> 1) & 3)) << 4);
                uint32_t ah[4], al[4];
                LDMX4(ah, ab + sw);
#pragma unroll
                for (int nf = 0; nf < 4; nf++) {
                    MMA16816(C[mf][nf], ah, bhi[nf][0], bhi[nf][1]);
                    MMA16816(C[mf][nf], ah, blo[nf][0], blo[nf][1]);
                }
                if (three) {
                    LDMX4(al, ab + 8192u + sw);
#pragma unroll
                    for (int nf = 0; nf < 4; nf++)
                        MMA16816(C[mf][nf], al, bhi[nf][0], bhi[nf][1]);
                }
            }
        }
    }

    // ---------------- epilogue ----------------
#pragma unroll
    for (int mf = 0; mf < 4; mf++) {
#pragma unroll
        for (int nf = 0; nf < 4; nf++) {
            int row0 = m0 + wm * 64 + mf * 16 + (lane >> 2);
            int col  = n0 + wn * 32 + nf * 8 + (lane & 3) * 2;   // even
            if (mode == 0) {
                *(float2*)(OUT + (size_t)row0 * DM + col) =
                    make_float2(C[mf][nf][0], C[mf][nf][1]);
                *(float2*)(OUT + (size_t)(row0 + 8) * DM + col) =
                    make_float2(C[mf][nf][2], C[mf][nf][3]);
            } else {
                const int which = col >> 10;
                const int h  = (col & 1023) >> 6;
                const int dd = col & 63;
                if (which == 2) {
#pragma unroll
                    for (int rr = 0; rr < 2; rr++) {
                        int row = row0 + rr * 8;
                        int b = row >> 11, s = row & 2047;
                        float* vp = g_v + (((size_t)(b * NH + h) * SEQ + s) * HD) + dd;
                        *(float2*)vp = make_float2(C[mf][nf][2*rr], C[mf][nf][2*rr+1]);
                    }
                } else {
                    // Q/K: RoPE (neg-sin interleaved, validated r6) + split
                    __half* dhi = (which == 0) ? s_qhi : s_khi;
                    __half* dlo = (which == 0) ? s_qlo : s_klo;
                    const float inv_f = expf((float)dd * -0.14391156831212787f);
#pragma unroll
                    for (int rr = 0; rr < 2; rr++) {
                        int row = row0 + rr * 8;
                        int b = row >> 11, s = row & 2047;
                        float cs, sn;
                        sincosf((float)s * inv_f, &cs, &sn);
                        float x0 = C[mf][nf][2*rr], x1 = C[mf][nf][2*rr+1];
                        float y0 = x0 * cs + x1 * sn;
                        float y1 = x1 * cs - x0 * sn;
                        uint32_t hi, lo;
                        split2(y0, y1, hi, lo);
                        size_t off = (((size_t)(b * NH + h) * SEQ + s) * HD) + dd;
                        *(uint32_t*)(dhi + off) = hi;
                        *(uint32_t*)(dlo + off) = lo;
                    }
                }
            }
        }
    }
}

// ---------------------------------------------------------------------------
// V transpose + split: g_v fp32 [bh][s][d] -> s_vthi/s_vtlo [bh][d][s]
// ---------------------------------------------------------------------------
__global__ __launch_bounds__(256) void transpose_v() {
    __shared__ float t[64][65];
    const int bh = blockIdx.x, s0 = blockIdx.y * 64;
    const int tid = threadIdx.x;
    const float* src = g_v + (size_t)bh * SEQ * HD + (size_t)s0 * HD;
#pragma unroll
    for (int i = 0; i < 4; i++) {
        int idx = tid + i * 256;
        int rr = idx >> 4, cc = (idx & 15) << 2;
        float4 v = *(const float4*)(src + rr * HD + cc);
        t[rr][cc] = v.x; t[rr][cc+1] = v.y; t[rr][cc+2] = v.z; t[rr][cc+3] = v.w;
    }
    __syncthreads();
    __half* dhi = s_vthi + (size_t)bh * HD * SEQ + s0;
    __half* dlo = s_vtlo + (size_t)bh * HD * SEQ + s0;
#pragma unroll
    for (int i = 0; i < 8; i++) {
        int idx = tid + i * 256;
        int d = idx >> 5, sp = (idx & 31) << 1;
        uint32_t hi, lo;
        split2(t[sp][d], t[sp+1][d], hi, lo);
        *(uint32_t*)(dhi + (size_t)d * SEQ + sp) = hi;
        *(uint32_t*)(dlo + (size_t)d * SEQ + sp) = lo;
    }
}

// ---------------------------------------------------------------------------
// Flash attention, split-fp16 mma.sync. S: 3-product (logit precision).
// PV: 2-product (P_hi only — P in (0,1], linear path). Base-2 softmax,
// single barrier/tile, warp diagonal skip, heavy-first grid.
// ---------------------------------------------------------------------------
#define AT_SMEM (32768 + 2*32768)
#define SCL2 0.18033688011112042f   /* 0.125 * log2(e) */

__device__ __forceinline__ void at_stage64(uint32_t dst, const __half* src,
                                           int rowstride, int tid) {
#pragma unroll
    for (int t = 0; t < 2; t++) {
        int idx = tid + t * 256;
        int row = idx >> 3, c16 = idx & 7;
        const void* gp = src + (size_t)row * rowstride + c16 * 8;
        uint32_t sa = dst + (uint32_t)(row * 128 + ((c16 ^ (row & 7)) << 4));
        CPASYNC16(sa, gp);
    }
}

__global__ __launch_bounds__(256, 2) void attn_mma() {
    extern __shared__ __align__(128) char smraw[];
    const uint32_t sb = smem_u32(smraw);
    const int tid = threadIdx.x;
    const int wid = tid >> 5;
    const int lane = tid & 31;
    const int bh = blockIdx.x;
    const int qt = 15 - blockIdx.y;           // heavy tiles first
    const int q0 = qt * 128;
    const int nkt = 2 * qt + 2;

    const size_t qk_off = (size_t)bh * SEQ * HD;
    const size_t vt_off = (size_t)bh * HD * SEQ;

#pragma unroll
    for (int t = 0; t < 4; t++) {
        int idx = tid + t * 256;
        int row = idx >> 3, c16 = idx & 7;
        uint32_t sw = (uint32_t)(row * 128 + ((c16 ^ (row & 7)) << 4));
        CPASYNC16(sb + sw, s_qhi + qk_off + (size_t)(q0 + row) * HD + c16 * 8);
        CPASYNC16(sb + 16384u + sw, s_qlo + qk_off + (size_t)(q0 + row) * HD + c16 * 8);
    }
    {
        uint32_t d0 = sb + 32768u;
        at_stage64(d0,           s_khi + qk_off, HD, tid);
        at_stage64(d0 + 8192u,   s_klo + qk_off, HD, tid);
        at_stage64(d0 + 16384u,  s_vthi + vt_off, SEQ, tid);
        at_stage64(d0 + 24576u,  s_vtlo + vt_off, SEQ, tid);
    }
    asm volatile("cp.async.commit_group;" ::: "memory");

    float O[8][4];
#pragma unroll
    for (int nf = 0; nf < 8; nf++)
#pragma unroll
        for (int j = 0; j < 4; j++) O[nf][j] = 0.f;
    float m0 = -1e30f, m1 = -1e30f, l0 = 0.f, l1 = 0.f;

    const int r0g = q0 + wid * 16 + (lane >> 2);
    const int arow = wid * 16 + ((lane >> 3) & 1) * 8 + (lane & 7);
    const int brow_b = (lane & 7) + (lane >> 4) * 8;
    const int bsel = (lane >> 3) & 1;
    const int asel = lane >> 4;

    for (int kt = 0; kt < nkt; kt++) {
        const int p = kt & 1;
        const int k0 = kt * 64;
        asm volatile("cp.async.wait_group 0;" ::: "memory");
        __syncthreads();
        if (kt + 1 < nkt) {
            uint32_t dn = sb + 32768u + (uint32_t)(p ^ 1) * 32768u;
            int kn = (kt + 1) * 64;
            at_stage64(dn,          s_khi + qk_off + (size_t)kn * HD, HD, tid);
            at_stage64(dn + 8192u,  s_klo + qk_off + (size_t)kn * HD, HD, tid);
            at_stage64(dn + 16384u, s_vthi + vt_off + kn, SEQ, tid);
            at_stage64(dn + 24576u, s_vtlo + vt_off + kn, SEQ, tid);
            asm volatile("cp.async.commit_group;" ::: "memory");
        }

        if (q0 + wid * 16 + 15 < k0) continue;   // fully masked for this warp

        const uint32_t kb = sb + 32768u + (uint32_t)p * 32768u;

        float S[8][4];
#pragma unroll
        for (int nf = 0; nf < 8; nf++)
#pragma unroll
            for (int j = 0; j < 4; j++) S[nf][j] = 0.f;
#pragma unroll
        for (int kh = 0; kh < 4; kh++) {
            int ac16 = 2 * kh + asel;
            uint32_t aoff = (uint32_t)(arow * 128 + ((ac16 ^ (arow & 7)) << 4));
            uint32_t qh[4], ql[4];
            LDMX4(qh, sb + aoff);
            LDMX4(ql, sb + 16384u + aoff);
            int bc16 = 2 * kh + bsel;
#pragma unroll
            for (int bp = 0; bp < 4; bp++) {
                int brow = bp * 16 + brow_b;
                uint32_t boff = (uint32_t)(brow * 128 + ((bc16 ^ (brow & 7)) << 4));
                uint32_t th[4], tl[4];
                LDMX4(th, kb + boff);
                LDMX4(tl, kb + 8192u + boff);
                MMA16816(S[2*bp],   qh, th[0], th[1]);
                MMA16816(S[2*bp+1], qh, th[2], th[3]);
                MMA16816(S[2*bp],   qh, tl[0], tl[1]);
                MMA16816(S[2*bp+1], qh, tl[2], tl[3]);
                MMA16816(S[2*bp],   ql, th[0], th[1]);
                MMA16816(S[2*bp+1], ql, th[2], th[3]);
            }
        }

        // scale into base-2 domain + causal mask
        const bool msk = (k0 >= q0);
#pragma unroll
        for (int nf = 0; nf < 8; nf++)
#pragma unroll
            for (int j = 0; j < 4; j++) {
                float sv = S[nf][j] * SCL2;
                if (msk) {
                    int col = k0 + nf * 8 + (lane & 3) * 2 + (j & 1);
                    int row = (j < 2) ? r0g : r0g + 8;
                    if (col > row) sv = -1e30f;
                }
                S[nf][j] = sv;
            }

        float tm0 = -1e30f, tm1 = -1e30f;
#pragma unroll
        for (int nf = 0; nf < 8; nf++) {
            tm0 = fmaxf(tm0, fmaxf(S[nf][0], S[nf][1]));
            tm1 = fmaxf(tm1, fmaxf(S[nf][2], S[nf][3]));
        }
        tm0 = fmaxf(tm0, __shfl_xor_sync(0xffffffffu, tm0, 1));
        tm0 = fmaxf(tm0, __shfl_xor_sync(0xffffffffu, tm0, 2));
        tm1 = fmaxf(tm1, __shfl_xor_sync(0xffffffffu, tm1, 1));
        tm1 = fmaxf(tm1, __shfl_xor_sync(0xffffffffu, tm1, 2));
        float mn0 = fmaxf(m0, tm0), mn1 = fmaxf(m1, tm1);
        float f0 = exp2f(m0 - mn0), f1 = exp2f(m1 - mn1);
        m0 = mn0; m1 = mn1;
        float rs0 = 0.f, rs1 = 0.f;
#pragma unroll
        for (int nf = 0; nf < 8; nf++) {
            S[nf][0] = exp2f(S[nf][0] - mn0); rs0 += S[nf][0];
            S[nf][1] = exp2f(S[nf][1] - mn0); rs0 += S[nf][1];
            S[nf][2] = exp2f(S[nf][2] - mn1); rs1 += S[nf][2];
            S[nf][3] = exp2f(S[nf][3] - mn1); rs1 += S[nf][3];
        }
        rs0 += __shfl_xor_sync(0xffffffffu, rs0, 1);
        rs0 += __shfl_xor_sync(0xffffffffu, rs0, 2);
        rs1 += __shfl_xor_sync(0xffffffffu, rs1, 1);
        rs1 += __shfl_xor_sync(0xffffffffu, rs1, 2);
        l0 = l0 * f0 + rs0;
        l1 = l1 * f1 + rs1;
#pragma unroll
        for (int nf = 0; nf < 8; nf++) {
            O[nf][0] *= f0; O[nf][1] *= f0;
            O[nf][2] *= f1; O[nf][3] *= f1;
        }

        // PV: 2-product (P_hi only; P in (0,1], lo term ~2^-12 relative)
#pragma unroll
        for (int kk = 0; kk < 4; kk++) {
            uint32_t ah[4];
            ah[0] = pack_h2(S[2*kk][0],   S[2*kk][1]);
            ah[1] = pack_h2(S[2*kk][2],   S[2*kk][3]);
            ah[2] = pack_h2(S[2*kk+1][0], S[2*kk+1][1]);
            ah[3] = pack_h2(S[2*kk+1][2], S[2*kk+1][3]);
            int bc16 = 2 * kk + bsel;
#pragma unroll
            for (int bp = 0; bp < 4; bp++) {
                int brow = bp * 16 + brow_b;
                uint32_t boff = (uint32_t)(brow * 128 + ((bc16 ^ (brow & 7)) << 4));
                uint32_t vh[4], vl[4];
                LDMX4(vh, kb + 16384u + boff);
                LDMX4(vl, kb + 24576u + boff);
                MMA16816(O[2*bp],   ah, vh[0], vh[1]);
                MMA16816(O[2*bp+1], ah, vh[2], vh[3]);
                MMA16816(O[2*bp],   ah, vl[0], vl[1]);
                MMA16816(O[2*bp+1], ah, vl[2], vl[3]);
            }
        }
    }

    const int b = bh >> 4, h = bh & 15;
    const float inv0 = 1.0f / l0, inv1 = 1.0f / l1;
    const size_t mrow0 = (size_t)(b * SEQ + r0g) * DM;
    const size_t mrow1 = (size_t)(b * SEQ + r0g + 8) * DM;
    const int colb = h * HD + (lane & 3) * 2;
#pragma unroll
    for (int nf = 0; nf < 8; nf++) {
        int col = colb + nf * 8;
        uint32_t hi, lo;
        split2(O[nf][0] * inv0, O[nf][1] * inv0, hi, lo);
        *(uint32_t*)(s_ahi + mrow0 + col) = hi;
        *(uint32_t*)(s_alo + mrow0 + col) = lo;
        split2(O[nf][2] * inv1, O[nf][3] * inv1, hi, lo);
        *(uint32_t*)(s_ahi + mrow1 + col) = hi;
        *(uint32_t*)(s_alo + mrow1 + col) = lo;
    }
}

// ---------------------------------------------------------------------------
extern "C" void kernel_launch(void* const* d_in, const int* in_sizes, int n_in,
                              void* d_out, int out_size) {
    (void)out_size;
    const float* x = (const float*)d_in[0];
    const float* w_qkv = (const float*)d_in[1];
    const float* w_out = (const float*)d_in[2];
    for (int i = 0; i < n_in; i++) {
        if (in_sizes[i] == 8388608)      x     = (const float*)d_in[i];
        else if (in_sizes[i] == 3145728) w_qkv = (const float*)d_in[i];
        else if (in_sizes[i] == 1048576) w_out = (const float*)d_in[i];
    }
    float* out = (float*)d_out;

    void *p_xhi, *p_xlo, *p_whi, *p_wlo, *p_ohi, *p_olo, *p_ahi, *p_alo;
    cudaGetSymbolAddress(&p_xhi, s_xhi);
    cudaGetSymbolAddress(&p_xlo, s_xlo);
    cudaGetSymbolAddress(&p_whi, s_whi);
    cudaGetSymbolAddress(&p_wlo, s_wlo);
    cudaGetSymbolAddress(&p_ohi, s_ohi);
    cudaGetSymbolAddress(&p_olo, s_olo);
    cudaGetSymbolAddress(&p_ahi, s_ahi);
    cudaGetSymbolAddress(&p_alo, s_alo);

    cudaFuncSetAttribute(gemm_mma, cudaFuncAttributeMaxDynamicSharedMemorySize, GEMM_SMEM);
    cudaFuncSetAttribute(attn_mma, cudaFuncAttributeMaxDynamicSharedMemorySize, AT_SMEM);

    cvt_split3<<<(N_X + N_W + N_O) / 1024, 256>>>(x, w_qkv, w_out);

    gemm_mma<<<dim3(3*DM/128, MTOT/128), 256, GEMM_SMEM>>>(
        (const __half*)p_xhi, (const __half*)p_xlo,
        (const __half*)p_whi, (const __half*)p_wlo, nullptr, 1);

    transpose_v<<<dim3(BATCH*NH, SEQ/64), 256>>>();

    attn_mma<<<dim3(BATCH*NH, SEQ/128), 256, AT_SMEM>>>();

    gemm_mma<<<dim3(DM/128, MTOT/128), 256, GEMM_SMEM>>>(
        (const __half*)p_ahi, (const __half*)p_alo,
        (const __half*)p_ohi, (const __half*)p_olo, out, 0);
}

// round 17
// speedup vs baseline: 1.2109x; 1.0800x over previous
#include <cuda_runtime.h>
#include <cuda_fp16.h>
#include <math.h>
#include <stdint.h>

#define BATCH 4
#define SEQ   2048
#define DM    1024
#define NH    16
#define HD    64
#define MTOT  (BATCH*SEQ)   // 8192

// ---------------- scratch (__device__ statics; allocation-guard safe) -------
__device__ float g_v[(size_t)BATCH*NH*SEQ*HD];

__device__ __half s_xhi[(size_t)MTOT*DM];
__device__ __half s_xlo[(size_t)MTOT*DM];
__device__ __half s_whi[(size_t)3*DM*DM];
__device__ __half s_wlo[(size_t)3*DM*DM];
__device__ __half s_ohi[(size_t)DM*DM];
__device__ __half s_olo[(size_t)DM*DM];
__device__ __half s_ahi[(size_t)MTOT*DM];

__device__ __half s_qhi[(size_t)BATCH*NH*SEQ*HD];
__device__ __half s_qlo[(size_t)BATCH*NH*SEQ*HD];
__device__ __half s_khi[(size_t)BATCH*NH*SEQ*HD];
__device__ __half s_klo[(size_t)BATCH*NH*SEQ*HD];
__device__ __half s_vthi[(size_t)BATCH*NH*HD*SEQ];  // [bh][d][s]

// ---------------- helpers ----------------------------------------------------
__device__ __forceinline__ uint32_t smem_u32(const void* p) {
    uint32_t a;
    asm("{ .reg .u64 t; cvta.to.shared.u64 t, %1; cvt.u32.u64 %0, t; }"
        : "=r"(a) : "l"(p));
    return a;
}
#define LDMX4(d, a) \
    asm volatile("ldmatrix.sync.aligned.m8n8.x4.shared.b16 {%0,%1,%2,%3}, [%4];" \
                 : "=r"((d)[0]), "=r"((d)[1]), "=r"((d)[2]), "=r"((d)[3]) : "r"(a))
#define MMA16816(c, a, b0, b1) \
    asm volatile("mma.sync.aligned.m16n8k16.row.col.f32.f16.f16.f32 " \
                 "{%0,%1,%2,%3}, {%4,%5,%6,%7}, {%8,%9}, {%0,%1,%2,%3};" \
                 : "+f"((c)[0]), "+f"((c)[1]), "+f"((c)[2]), "+f"((c)[3]) \
                 : "r"((a)[0]), "r"((a)[1]), "r"((a)[2]), "r"((a)[3]), \
                   "r"(b0), "r"(b1))
#define CPASYNC16(sa, gp) \
    asm volatile("cp.async.cg.shared.global [%0], [%1], 16;" :: "r"(sa), "l"(gp))

__device__ __forceinline__ uint32_t pack_h2(float a, float b) {
    __half2 t = __floats2half2_rn(a, b);
    return *reinterpret_cast<uint32_t*>(&t);
}
__device__ __forceinline__ void split2(float a, float b, uint32_t& hi, uint32_t& lo) {
    __half ah = __float2half_rn(a), bh = __float2half_rn(b);
    __half2 h = __halves2half2(ah, bh);
    hi = *reinterpret_cast<uint32_t*>(&h);
    lo = pack_h2(a - __half2float(ah), b - __half2float(bh));
}

// ---------------------------------------------------------------------------
// fp32 -> fp16 hi/lo split of all three inputs, ONE launch, float4 vectorized
// ---------------------------------------------------------------------------
#define N_X (MTOT*DM)        // 8388608
#define N_W (3*DM*DM)        // 3145728
#define N_O (DM*DM)          // 1048576

__global__ __launch_bounds__(256) void cvt_split3(
    const float* __restrict__ x, const float* __restrict__ wq,
    const float* __restrict__ wo)
{
    int i4 = blockIdx.x * 256 + threadIdx.x;   // float4 index
    int i = i4 * 4;
    const float* src;
    __half *hi, *lo;
    int j;
    if (i < N_X)              { src = x;  hi = s_xhi; lo = s_xlo; j = i; }
    else if (i < N_X + N_W)   { src = wq; hi = s_whi; lo = s_wlo; j = i - N_X; }
    else                      { src = wo; hi = s_ohi; lo = s_olo; j = i - N_X - N_W; }
    float4 v = *(const float4*)(src + j);
    uint32_t h0, l0, h1, l1;
    split2(v.x, v.y, h0, l0);
    split2(v.z, v.w, h1, l1);
    *(uint2*)(hi + j) = make_uint2(h0, h1);
    *(uint2*)(lo + j) = make_uint2(l0, l1);
}

// ---------------------------------------------------------------------------
// Split-fp16 tensor-core GEMM. 2-stage, one barrier per chunk.
// mode 0: OUT store, 2-product (A_lo not staged/read).
// mode 1: 3-product; q/k -> RoPE+split; v -> g_v fp32.
// ---------------------------------------------------------------------------
#define GEMM_SMEM 65536

__device__ __forceinline__ void stage_chunk(
    uint32_t smbase, int p, int c,
    const __half* s0, const __half* s1,
    const __half* s2, const __half* s3, int tid, bool with_alo)
{
    const __half* srcs[4] = {s0, s1, s2, s3};
    const uint32_t bufb = smbase + (uint32_t)p * 32768u;
#pragma unroll
    for (int comp = 0; comp < 4; comp++) {
        if (comp == 1 && !with_alo) continue;   // skip A_lo in 2-product mode
        const __half* s = srcs[comp] + c * 32;
        const uint32_t db = bufb + (uint32_t)comp * 8192u;
#pragma unroll
        for (int t = 0; t < 2; t++) {
            int idx = tid + t * 256;
            int row = idx >> 2, c16 = idx & 3;
            const void* gp = s + (size_t)row * DM + c16 * 8;
            uint32_t sw = db + (uint32_t)(row * 64)
                        + ((uint32_t)(c16 ^ ((row >> 1) & 3)) << 4);
            CPASYNC16(sw, gp);
        }
    }
    asm volatile("cp.async.commit_group;" ::: "memory");
}

__global__ __launch_bounds__(256, 2) void gemm_mma(
    const __half* __restrict__ Ahi, const __half* __restrict__ Alo,
    const __half* __restrict__ Bhi, const __half* __restrict__ Blo,
    float* __restrict__ OUT, int mode)
{
    extern __shared__ __align__(128) char smraw[];
    const uint32_t smbase = smem_u32(smraw);
    const int tid  = threadIdx.x;
    const int wid  = tid >> 5;
    const int lane = tid & 31;
    const int wm   = wid >> 2;
    const int wn   = wid & 3;
    const int n0   = blockIdx.x * 128;
    const int m0   = blockIdx.y * 128;
    const bool three = (mode != 0);

    const __half* gAhi = Ahi + (size_t)m0 * DM;
    const __half* gAlo = Alo ? (Alo + (size_t)m0 * DM) : nullptr;
    const __half* gBhi = Bhi + (size_t)n0 * DM;
    const __half* gBlo = Blo + (size_t)n0 * DM;

    float C[4][4][4];
#pragma unroll
    for (int i = 0; i < 4; i++)
#pragma unroll
        for (int j = 0; j < 4; j++)
#pragma unroll
            for (int k = 0; k < 4; k++) C[i][j][k] = 0.f;

    const int g = lane >> 3, r = lane & 7;

    stage_chunk(smbase, 0, 0, gAhi, gAlo, gBhi, gBlo, tid, three);

    for (int c = 0; c < 32; c++) {
        const int p = c & 1;
        asm volatile("cp.async.wait_group 0;" ::: "memory");
        __syncthreads();
        if (c + 1 < 32)
            stage_chunk(smbase, p ^ 1, c + 1, gAhi, gAlo, gBhi, gBlo, tid, three);

        const uint32_t ab = smbase + (uint32_t)p * 32768u;
#pragma unroll
        for (int kh = 0; kh < 2; kh++) {
            const int kkc = kh * 2;
            uint32_t bhi[4][2], blo[4][2];
#pragma unroll
            for (int bp = 0; bp < 2; bp++) {
                int row = wn * 32 + bp * 16 + (g >> 1) * 8 + r;
                int c16 = kkc + (g & 1);
                uint32_t sw = (uint32_t)(row * 64)
                            + ((uint32_t)(c16 ^ ((row >> 1) & 3)) << 4);
                uint32_t t[4];
                LDMX4(t, ab + 16384u + sw);
                bhi[bp*2][0] = t[0]; bhi[bp*2][1] = t[1];
                bhi[bp*2+1][0] = t[2]; bhi[bp*2+1][1] = t[3];
                LDMX4(t, ab + 24576u + sw);
                blo[bp*2][0] = t[0]; blo[bp*2][1] = t[1];
                blo[bp*2+1][0] = t[2]; blo[bp*2+1][1] = t[3];
            }
#pragma unroll
            for (int mf = 0; mf < 4; mf++) {
                int row = wm * 64 + mf * 16 + (g & 1) * 8 + r;
                int c16 = kkc + (g >> 1);
                uint32_t sw = (uint32_t)(row * 64)
                            + ((uint32_t)(c16 ^ ((row >> 1) & 3)) << 4);
                uint32_t ah[4], al[4];
                LDMX4(ah, ab + sw);
#pragma unroll
                for (int nf = 0; nf < 4; nf++) {
                    MMA16816(C[mf][nf], ah, bhi[nf][0], bhi[nf][1]);
                    MMA16816(C[mf][nf], ah, blo[nf][0], blo[nf][1]);
                }
                if (three) {
                    LDMX4(al, ab + 8192u + sw);
#pragma unroll
                    for (int nf = 0; nf < 4; nf++)
                        MMA16816(C[mf][nf], al, bhi[nf][0], bhi[nf][1]);
                }
            }
        }
    }

    // ---------------- epilogue ----------------
#pragma unroll
    for (int mf = 0; mf < 4; mf++) {
#pragma unroll
        for (int nf = 0; nf < 4; nf++) {
            int row0 = m0 + wm * 64 + mf * 16 + (lane >> 2);
            int col  = n0 + wn * 32 + nf * 8 + (lane & 3) * 2;   // even
            if (mode == 0) {
                *(float2*)(OUT + (size_t)row0 * DM + col) =
                    make_float2(C[mf][nf][0], C[mf][nf][1]);
                *(float2*)(OUT + (size_t)(row0 + 8) * DM + col) =
                    make_float2(C[mf][nf][2], C[mf][nf][3]);
            } else {
                const int which = col >> 10;
                const int h  = (col & 1023) >> 6;
                const int dd = col & 63;
                if (which == 2) {
#pragma unroll
                    for (int rr = 0; rr < 2; rr++) {
                        int row = row0 + rr * 8;
                        int b = row >> 11, s = row & 2047;
                        float* vp = g_v + (((size_t)(b * NH + h) * SEQ + s) * HD) + dd;
                        *(float2*)vp = make_float2(C[mf][nf][2*rr], C[mf][nf][2*rr+1]);
                    }
                } else {
                    // Q/K: RoPE (neg-sin interleaved, validated r6) + split
                    __half* dhi = (which == 0) ? s_qhi : s_khi;
                    __half* dlo = (which == 0) ? s_qlo : s_klo;
                    const float inv_f = expf((float)dd * -0.14391156831212787f);
#pragma unroll
                    for (int rr = 0; rr < 2; rr++) {
                        int row = row0 + rr * 8;
                        int b = row >> 11, s = row & 2047;
                        float cs, sn;
                        sincosf((float)s * inv_f, &cs, &sn);
                        float x0 = C[mf][nf][2*rr], x1 = C[mf][nf][2*rr+1];
                        float y0 = x0 * cs + x1 * sn;
                        float y1 = x1 * cs - x0 * sn;
                        uint32_t hi, lo;
                        split2(y0, y1, hi, lo);
                        size_t off = (((size_t)(b * NH + h) * SEQ + s) * HD) + dd;
                        *(uint32_t*)(dhi + off) = hi;
                        *(uint32_t*)(dlo + off) = lo;
                    }
                }
            }
        }
    }
}

// ---------------------------------------------------------------------------
// V transpose: g_v fp32 [bh][s][d] -> s_vthi fp16 [bh][d][s] (hi only)
// ---------------------------------------------------------------------------
__global__ __launch_bounds__(256) void transpose_v() {
    __shared__ float t[64][65];
    const int bh = blockIdx.x, s0 = blockIdx.y * 64;
    const int tid = threadIdx.x;
    const float* src = g_v + (size_t)bh * SEQ * HD + (size_t)s0 * HD;
#pragma unroll
    for (int i = 0; i < 4; i++) {
        int idx = tid + i * 256;
        int rr = idx >> 4, cc = (idx & 15) << 2;
        float4 v = *(const float4*)(src + rr * HD + cc);
        t[rr][cc] = v.x; t[rr][cc+1] = v.y; t[rr][cc+2] = v.z; t[rr][cc+3] = v.w;
    }
    __syncthreads();
    __half* dhi = s_vthi + (size_t)bh * HD * SEQ + s0;
#pragma unroll
    for (int i = 0; i < 8; i++) {
        int idx = tid + i * 256;
        int d = idx >> 5, sp = (idx & 31) << 1;
        *(uint32_t*)(dhi + (size_t)d * SEQ + sp) = pack_h2(t[sp][d], t[sp+1][d]);
    }
}

// ---------------------------------------------------------------------------
// Flash attention, split-fp16 mma.sync. S: 3-product. PV: 1-product
// (P_hi x V_hi — both roundings same magnitude, linear path). Base-2 softmax,
// single barrier/tile, warp diagonal skip, heavy-first grid.
// Stage layout: Khi 8K | Klo 8K | Vhi 8K = 24K per stage.
// ---------------------------------------------------------------------------
#define AT_SMEM (32768 + 2*24576)
#define SCL2 0.18033688011112042f   /* 0.125 * log2(e) */

__device__ __forceinline__ void at_stage64(uint32_t dst, const __half* src,
                                           int rowstride, int tid) {
#pragma unroll
    for (int t = 0; t < 2; t++) {
        int idx = tid + t * 256;
        int row = idx >> 3, c16 = idx & 7;
        const void* gp = src + (size_t)row * rowstride + c16 * 8;
        uint32_t sa = dst + (uint32_t)(row * 128 + ((c16 ^ (row & 7)) << 4));
        CPASYNC16(sa, gp);
    }
}

__global__ __launch_bounds__(256, 2) void attn_mma() {
    extern __shared__ __align__(128) char smraw[];
    const uint32_t sb = smem_u32(smraw);
    const int tid = threadIdx.x;
    const int wid = tid >> 5;
    const int lane = tid & 31;
    const int bh = blockIdx.x;
    const int qt = 15 - blockIdx.y;           // heavy tiles first
    const int q0 = qt * 128;
    const int nkt = 2 * qt + 2;

    const size_t qk_off = (size_t)bh * SEQ * HD;
    const size_t vt_off = (size_t)bh * HD * SEQ;

#pragma unroll
    for (int t = 0; t < 4; t++) {
        int idx = tid + t * 256;
        int row = idx >> 3, c16 = idx & 7;
        uint32_t sw = (uint32_t)(row * 128 + ((c16 ^ (row & 7)) << 4));
        CPASYNC16(sb + sw, s_qhi + qk_off + (size_t)(q0 + row) * HD + c16 * 8);
        CPASYNC16(sb + 16384u + sw, s_qlo + qk_off + (size_t)(q0 + row) * HD + c16 * 8);
    }
    {
        uint32_t d0 = sb + 32768u;
        at_stage64(d0,           s_khi + qk_off, HD, tid);
        at_stage64(d0 + 8192u,   s_klo + qk_off, HD, tid);
        at_stage64(d0 + 16384u,  s_vthi + vt_off, SEQ, tid);
    }
    asm volatile("cp.async.commit_group;" ::: "memory");

    float O[8][4];
#pragma unroll
    for (int nf = 0; nf < 8; nf++)
#pragma unroll
        for (int j = 0; j < 4; j++) O[nf][j] = 0.f;
    float m0 = -1e30f, m1 = -1e30f, l0 = 0.f, l1 = 0.f;

    const int r0g = q0 + wid * 16 + (lane >> 2);
    const int arow = wid * 16 + ((lane >> 3) & 1) * 8 + (lane & 7);
    const int brow_b = (lane & 7) + (lane >> 4) * 8;
    const int bsel = (lane >> 3) & 1;
    const int asel = lane >> 4;

    for (int kt = 0; kt < nkt; kt++) {
        const int p = kt & 1;
        const int k0 = kt * 64;
        asm volatile("cp.async.wait_group 0;" ::: "memory");
        __syncthreads();
        if (kt + 1 < nkt) {
            uint32_t dn = sb + 32768u + (uint32_t)(p ^ 1) * 24576u;
            int kn = (kt + 1) * 64;
            at_stage64(dn,          s_khi + qk_off + (size_t)kn * HD, HD, tid);
            at_stage64(dn + 8192u,  s_klo + qk_off + (size_t)kn * HD, HD, tid);
            at_stage64(dn + 16384u, s_vthi + vt_off + kn, SEQ, tid);
            asm volatile("cp.async.commit_group;" ::: "memory");
        }

        if (q0 + wid * 16 + 15 < k0) continue;   // fully masked for this warp

        const uint32_t kb = sb + 32768u + (uint32_t)p * 24576u;

        float S[8][4];
#pragma unroll
        for (int nf = 0; nf < 8; nf++)
#pragma unroll
            for (int j = 0; j < 4; j++) S[nf][j] = 0.f;
#pragma unroll
        for (int kh = 0; kh < 4; kh++) {
            int ac16 = 2 * kh + asel;
            uint32_t aoff = (uint32_t)(arow * 128 + ((ac16 ^ (arow & 7)) << 4));
            uint32_t qh[4], ql[4];
            LDMX4(qh, sb + aoff);
            LDMX4(ql, sb + 16384u + aoff);
            int bc16 = 2 * kh + bsel;
#pragma unroll
            for (int bp = 0; bp < 4; bp++) {
                int brow = bp * 16 + brow_b;
                uint32_t boff = (uint32_t)(brow * 128 + ((bc16 ^ (brow & 7)) << 4));
                uint32_t th[4], tl[4];
                LDMX4(th, kb + boff);
                LDMX4(tl, kb + 8192u + boff);
                MMA16816(S[2*bp],   qh, th[0], th[1]);
                MMA16816(S[2*bp+1], qh, th[2], th[3]);
                MMA16816(S[2*bp],   qh, tl[0], tl[1]);
                MMA16816(S[2*bp+1], qh, tl[2], tl[3]);
                MMA16816(S[2*bp],   ql, th[0], th[1]);
                MMA16816(S[2*bp+1], ql, th[2], th[3]);
            }
        }

        // scale into base-2 domain + causal mask
        const bool msk = (k0 >= q0);
#pragma unroll
        for (int nf = 0; nf < 8; nf++)
#pragma unroll
            for (int j = 0; j < 4; j++) {
                float sv = S[nf][j] * SCL2;
                if (msk) {
                    int col = k0 + nf * 8 + (lane & 3) * 2 + (j & 1);
                    int row = (j < 2) ? r0g : r0g + 8;
                    if (col > row) sv = -1e30f;
                }
                S[nf][j] = sv;
            }

        float tm0 = -1e30f, tm1 = -1e30f;
#pragma unroll
        for (int nf = 0; nf < 8; nf++) {
            tm0 = fmaxf(tm0, fmaxf(S[nf][0], S[nf][1]));
            tm1 = fmaxf(tm1, fmaxf(S[nf][2], S[nf][3]));
        }
        tm0 = fmaxf(tm0, __shfl_xor_sync(0xffffffffu, tm0, 1));
        tm0 = fmaxf(tm0, __shfl_xor_sync(0xffffffffu, tm0, 2));
        tm1 = fmaxf(tm1, __shfl_xor_sync(0xffffffffu, tm1, 1));
        tm1 = fmaxf(tm1, __shfl_xor_sync(0xffffffffu, tm1, 2));
        float mn0 = fmaxf(m0, tm0), mn1 = fmaxf(m1, tm1);
        float f0 = exp2f(m0 - mn0), f1 = exp2f(m1 - mn1);
        m0 = mn0; m1 = mn1;
        float rs0 = 0.f, rs1 = 0.f;
#pragma unroll
        for (int nf = 0; nf < 8; nf++) {
            S[nf][0] = exp2f(S[nf][0] - mn0); rs0 += S[nf][0];
            S[nf][1] = exp2f(S[nf][1] - mn0); rs0 += S[nf][1];
            S[nf][2] = exp2f(S[nf][2] - mn1); rs1 += S[nf][2];
            S[nf][3] = exp2f(S[nf][3] - mn1); rs1 += S[nf][3];
        }
        rs0 += __shfl_xor_sync(0xffffffffu, rs0, 1);
        rs0 += __shfl_xor_sync(0xffffffffu, rs0, 2);
        rs1 += __shfl_xor_sync(0xffffffffu, rs1, 1);
        rs1 += __shfl_xor_sync(0xffffffffu, rs1, 2);
        l0 = l0 * f0 + rs0;
        l1 = l1 * f1 + rs1;
#pragma unroll
        for (int nf = 0; nf < 8; nf++) {
            O[nf][0] *= f0; O[nf][1] *= f0;
            O[nf][2] *= f1; O[nf][3] *= f1;
        }

        // PV: 1-product (P_hi x V_hi)
#pragma unroll
        for (int kk = 0; kk < 4; kk++) {
            uint32_t ah[4];
            ah[0] = pack_h2(S[2*kk][0],   S[2*kk][1]);
            ah[1] = pack_h2(S[2*kk][2],   S[2*kk][3]);
            ah[2] = pack_h2(S[2*kk+1][0], S[2*kk+1][1]);
            ah[3] = pack_h2(S[2*kk+1][2], S[2*kk+1][3]);
            int bc16 = 2 * kk + bsel;
#pragma unroll
            for (int bp = 0; bp < 4; bp++) {
                int brow = bp * 16 + brow_b;
                uint32_t boff = (uint32_t)(brow * 128 + ((bc16 ^ (brow & 7)) << 4));
                uint32_t vh[4];
                LDMX4(vh, kb + 16384u + boff);
                MMA16816(O[2*bp],   ah, vh[0], vh[1]);
                MMA16816(O[2*bp+1], ah, vh[2], vh[3]);
            }
        }
    }

    const int b = bh >> 4, h = bh & 15;
    const float inv0 = 1.0f / l0, inv1 = 1.0f / l1;
    const size_t mrow0 = (size_t)(b * SEQ + r0g) * DM;
    const size_t mrow1 = (size_t)(b * SEQ + r0g + 8) * DM;
    const int colb = h * HD + (lane & 3) * 2;
#pragma unroll
    for (int nf = 0; nf < 8; nf++) {
        int col = colb + nf * 8;
        *(uint32_t*)(s_ahi + mrow0 + col) = pack_h2(O[nf][0] * inv0, O[nf][1] * inv0);
        *(uint32_t*)(s_ahi + mrow1 + col) = pack_h2(O[nf][2] * inv1, O[nf][3] * inv1);
    }
}

// ---------------------------------------------------------------------------
extern "C" void kernel_launch(void* const* d_in, const int* in_sizes, int n_in,
                              void* d_out, int out_size) {
    (void)out_size;
    const float* x = (const float*)d_in[0];
    const float* w_qkv = (const float*)d_in[1];
    const float* w_out = (const float*)d_in[2];
    for (int i = 0; i < n_in; i++) {
        if (in_sizes[i] == 8388608)      x     = (const float*)d_in[i];
        else if (in_sizes[i] == 3145728) w_qkv = (const float*)d_in[i];
        else if (in_sizes[i] == 1048576) w_out = (const float*)d_in[i];
    }
    float* out = (float*)d_out;

    void *p_xhi, *p_xlo, *p_whi, *p_wlo, *p_ohi, *p_olo, *p_ahi;
    cudaGetSymbolAddress(&p_xhi, s_xhi);
    cudaGetSymbolAddress(&p_xlo, s_xlo);
    cudaGetSymbolAddress(&p_whi, s_whi);
    cudaGetSymbolAddress(&p_wlo, s_wlo);
    cudaGetSymbolAddress(&p_ohi, s_ohi);
    cudaGetSymbolAddress(&p_olo, s_olo);
    cudaGetSymbolAddress(&p_ahi, s_ahi);

    cudaFuncSetAttribute(gemm_mma, cudaFuncAttributeMaxDynamicSharedMemorySize, GEMM_SMEM);
    cudaFuncSetAttribute(attn_mma, cudaFuncAttributeMaxDynamicSharedMemorySize, AT_SMEM);

    cvt_split3<<<(N_X + N_W + N_O) / 1024, 256>>>(x, w_qkv, w_out);

    gemm_mma<<<dim3(3*DM/128, MTOT/128), 256, GEMM_SMEM>>>(
        (const __half*)p_xhi, (const __half*)p_xlo,
        (const __half*)p_whi, (const __half*)p_wlo, nullptr, 1);

    transpose_v<<<dim3(BATCH*NH, SEQ/64), 256>>>();

    attn_mma<<<dim3(BATCH*NH, SEQ/128), 256, AT_SMEM>>>();

    gemm_mma<<<dim3(DM/128, MTOT/128), 256, GEMM_SMEM>>>(
        (const __half*)p_ahi, nullptr,
        (const __half*)p_ohi, (const __half*)p_olo, out, 0);
}